// round 1
// baseline (speedup 1.0000x reference)
#include <cuda_runtime.h>
#include <cstddef>

// Problem constants
#define LSEQ 2048
#define EDIM 512
#define HEADS 8
#define DDIM 64
#define E3   1536
#define CHUNK 128
#define NCH  16

// Scratch (device globals; no allocations allowed)
__device__ float g_qkv[LSEQ * E3];            // 12.6 MB
__device__ float g_attn[LSEQ * EDIM];         // 4 MB
__device__ float g_ckv[HEADS * NCH * 2 * DDIM * DDIM]; // per (h,chunk,branch) KV sums
__device__ float g_ck [HEADS * NCH * 2 * DDIM];        // per (h,chunk,branch) K sums
__device__ float g_pkv[HEADS * NCH * 2 * DDIM * DDIM]; // exclusive prefix
__device__ float g_pk [HEADS * NCH * 2 * DDIM];

#define THETA_SCALE 7.66990393942820573e-4f  // (pi/2)/2048

// ---------------------------------------------------------------------------
// Generic register-blocked SGEMM with bias: C[M,N] = A[M,K] @ B[K,N] + bias[N]
// Dimensions assumed divisible by tile sizes (true for all uses here).
// ---------------------------------------------------------------------------
template<int BM, int BN, int BK, int TM, int TN>
__global__ __launch_bounds__(256)
void sgemm_bias(const float* __restrict__ A, const float* __restrict__ B,
                const float* __restrict__ bias, float* __restrict__ C,
                int M, int N, int K) {
    __shared__ float As[BK][BM];   // A tile stored transposed
    __shared__ float Bs[BK][BN];

    const int tid = threadIdx.x;          // 256 threads
    const int tx = tid & 15;              // 16 x 16 thread grid
    const int ty = tid >> 4;
    const int bn0 = blockIdx.x * BN;
    const int bm0 = blockIdx.y * BM;

    float acc[TM][TN];
    #pragma unroll
    for (int i = 0; i < TM; i++)
        #pragma unroll
        for (int j = 0; j < TN; j++) acc[i][j] = 0.f;

    const float* Ab = A + (size_t)bm0 * K;
    const float* Bb = B + bn0;

    for (int k0 = 0; k0 < K; k0 += BK) {
        // Load A tile (BM x BK) as float4, store transposed
        #pragma unroll
        for (int li = tid; li < BM * BK / 4; li += 256) {
            int row = li / (BK / 4);
            int c4  = (li % (BK / 4)) * 4;
            float4 av = *reinterpret_cast<const float4*>(&Ab[(size_t)row * K + k0 + c4]);
            As[c4 + 0][row] = av.x;
            As[c4 + 1][row] = av.y;
            As[c4 + 2][row] = av.z;
            As[c4 + 3][row] = av.w;
        }
        // Load B tile (BK x BN) as float4
        #pragma unroll
        for (int li = tid; li < BK * BN / 4; li += 256) {
            int row = li / (BN / 4);
            int c4  = (li % (BN / 4)) * 4;
            *reinterpret_cast<float4*>(&Bs[row][c4]) =
                *reinterpret_cast<const float4*>(&Bb[(size_t)(k0 + row) * N + c4]);
        }
        __syncthreads();

        #pragma unroll
        for (int kk = 0; kk < BK; kk++) {
            float ar[TM], br[TN];
            #pragma unroll
            for (int i = 0; i < TM; i++) ar[i] = As[kk][ty * TM + i];
            #pragma unroll
            for (int j = 0; j < TN; j++) br[j] = Bs[kk][tx * TN + j];
            #pragma unroll
            for (int i = 0; i < TM; i++)
                #pragma unroll
                for (int j = 0; j < TN; j++)
                    acc[i][j] += ar[i] * br[j];
        }
        __syncthreads();
    }

    #pragma unroll
    for (int i = 0; i < TM; i++) {
        int r = bm0 + ty * TM + i;
        float* cp = C + (size_t)r * N + bn0 + tx * TN;
        const float* bp = bias + bn0 + tx * TN;
        #pragma unroll
        for (int j = 0; j < TN; j++) cp[j] = acc[i][j] + bp[j];
    }
}

// ---------------------------------------------------------------------------
// Per-chunk KV / K sums for both cos and sin branches.
// grid: (NCH, HEADS), 256 threads. dyn smem = (2*128*64 + 256) floats
// ---------------------------------------------------------------------------
__global__ __launch_bounds__(256)
void chunk_sum_kernel() {
    extern __shared__ float sm[];
    float* rk = sm;              // 128 x 64 (relu'd K)
    float* vv = rk + CHUNK * DDIM; // 128 x 64 (V)
    float* cw = vv + CHUNK * DDIM; // 128
    float* sw = cw + CHUNK;        // 128

    const int c = blockIdx.x, h = blockIdx.y, tid = threadIdx.x;

    for (int t = tid; t < CHUNK * DDIM; t += 256) {
        int i = t >> 6, d = t & 63;
        const float* row = g_qkv + (size_t)(c * CHUNK + i) * E3 + h * DDIM;
        rk[t] = fmaxf(row[EDIM + d], 0.f);
        vv[t] = row[2 * EDIM + d];
    }
    if (tid < CHUNK) {
        float th = (float)(c * CHUNK + tid) * THETA_SCALE;
        cw[tid] = cosf(th);
        sw[tid] = sinf(th);
    }
    __syncthreads();

    // Each thread: fixed d, 16 consecutive e's
    const int d  = tid & 63;
    const int eg = (tid >> 6) << 4;  // 0,16,32,48
    float aC[16], aS[16];
    #pragma unroll
    for (int e = 0; e < 16; e++) { aC[e] = 0.f; aS[e] = 0.f; }

    for (int i = 0; i < CHUNK; i++) {
        float kd = rk[i * DDIM + d];
        float kc = kd * cw[i];
        float ks = kd * sw[i];
        const float4* vp = reinterpret_cast<const float4*>(&vv[i * DDIM + eg]);
        #pragma unroll
        for (int e4 = 0; e4 < 4; e4++) {
            float4 v4 = vp[e4];
            aC[e4 * 4 + 0] += kc * v4.x; aC[e4 * 4 + 1] += kc * v4.y;
            aC[e4 * 4 + 2] += kc * v4.z; aC[e4 * 4 + 3] += kc * v4.w;
            aS[e4 * 4 + 0] += ks * v4.x; aS[e4 * 4 + 1] += ks * v4.y;
            aS[e4 * 4 + 2] += ks * v4.z; aS[e4 * 4 + 3] += ks * v4.w;
        }
    }

    size_t base = (size_t)(h * NCH + c) * 2 * DDIM * DDIM;
    #pragma unroll
    for (int e = 0; e < 16; e++) {
        g_ckv[base + d * DDIM + eg + e]                 = aC[e];
        g_ckv[base + DDIM * DDIM + d * DDIM + eg + e]   = aS[e];
    }

    if (tid < DDIM) {
        float sc = 0.f, ss = 0.f;
        for (int i = 0; i < CHUNK; i++) {
            float kd = rk[i * DDIM + tid];
            sc += kd * cw[i];
            ss += kd * sw[i];
        }
        size_t kb = (size_t)(h * NCH + c) * 2 * DDIM;
        g_ck[kb + tid]        = sc;
        g_ck[kb + DDIM + tid] = ss;
    }
}

// ---------------------------------------------------------------------------
// Exclusive prefix scan over the 16 chunks (per head). grid: HEADS blocks.
// ---------------------------------------------------------------------------
__global__ __launch_bounds__(256)
void scan_kernel() {
    const int h = blockIdx.x, tid = threadIdx.x;
    const int KVSZ = 2 * DDIM * DDIM;  // 8192 per (h,chunk)
    for (int idx = tid; idx < KVSZ; idx += 256) {
        float run = 0.f;
        for (int c = 0; c < NCH; c++) {
            size_t off = (size_t)(h * NCH + c) * KVSZ + idx;
            g_pkv[off] = run;
            run += g_ckv[off];
        }
    }
    const int KSZ = 2 * DDIM; // 128
    if (tid < KSZ) {
        float run = 0.f;
        for (int c = 0; c < NCH; c++) {
            size_t off = (size_t)(h * NCH + c) * KSZ + tid;
            g_pk[off] = run;
            run += g_ck[off];
        }
    }
}

// ---------------------------------------------------------------------------
// Per-chunk output: prefix contribution + causal intra-chunk attention.
// grid: (NCH, HEADS), 256 threads, ~196 KB dyn smem.
// ---------------------------------------------------------------------------
#define RQT_STRIDE 132  // multiple of 4 for alignment

__global__ __launch_bounds__(256, 1)
void chunk_out_kernel() {
    extern __shared__ float sm[];
    float* rqT = sm;                      // [64][132] transposed relu(Q)
    float* rkT = rqT + DDIM * RQT_STRIDE; // [64][132] transposed relu(K)
    float* vv  = rkT + DDIM * RQT_STRIDE; // [128][64]
    float* S   = vv + CHUNK * DDIM;       // [128][128]
    float* KVc = S + CHUNK * CHUNK;       // [64][64]
    float* KVs = KVc + DDIM * DDIM;       // [64][64]
    float* K0c = KVs + DDIM * DDIM;       // [64]
    float* K0s = K0c + DDIM;              // [64]
    float* cw  = K0s + DDIM;              // [128]
    float* sw  = cw + CHUNK;              // [128]
    float* nrm = sw + CHUNK;              // [128]

    const int c = blockIdx.x, h = blockIdx.y, tid = threadIdx.x;

    // Load Q/K/V chunk (Q,K transposed; relu applied)
    for (int t = tid; t < CHUNK * DDIM; t += 256) {
        int i = t >> 6, d = t & 63;
        const float* row = g_qkv + (size_t)(c * CHUNK + i) * E3 + h * DDIM;
        rqT[d * RQT_STRIDE + i] = fmaxf(row[d], 0.f);
        rkT[d * RQT_STRIDE + i] = fmaxf(row[EDIM + d], 0.f);
        vv[i * DDIM + d]        = row[2 * EDIM + d];
    }
    if (tid < CHUNK) {
        float th = (float)(c * CHUNK + tid) * THETA_SCALE;
        cw[tid] = cosf(th);
        sw[tid] = sinf(th);
    }
    // Load prefix states
    {
        const float* base = g_pkv + (size_t)(h * NCH + c) * 2 * DDIM * DDIM;
        for (int t = tid; t < 2 * DDIM * DDIM; t += 256) {
            if (t < DDIM * DDIM) KVc[t] = base[t];
            else                 KVs[t - DDIM * DDIM] = base[t];
        }
        const float* kb = g_pk + (size_t)(h * NCH + c) * 2 * DDIM;
        if (tid < 2 * DDIM) {
            if (tid < DDIM) K0c[tid] = kb[tid];
            else            K0s[tid - DDIM] = kb[tid];
        }
    }
    __syncthreads();

    // ---- S = (RQ @ RK^T) * cos(theta_i - theta_j), causal; 8x8 register tiles
    {
        const int ti = tid >> 4, tj = tid & 15;
        const int i0 = ti * 8, j0 = tj * 8;
        if (j0 <= i0 + 7) {  // skip tiles fully above diagonal (never read)
            float acc[8][8];
            #pragma unroll
            for (int r = 0; r < 8; r++)
                #pragma unroll
                for (int q = 0; q < 8; q++) acc[r][q] = 0.f;

            for (int d = 0; d < DDIM; d++) {
                float a[8], b[8];
                #pragma unroll
                for (int r = 0; r < 8; r++) a[r] = rqT[d * RQT_STRIDE + i0 + r];
                #pragma unroll
                for (int r = 0; r < 8; r++) b[r] = rkT[d * RQT_STRIDE + j0 + r];
                #pragma unroll
                for (int r = 0; r < 8; r++)
                    #pragma unroll
                    for (int q = 0; q < 8; q++)
                        acc[r][q] += a[r] * b[q];
            }
            #pragma unroll
            for (int r = 0; r < 8; r++) {
                int i = i0 + r;
                float ci = cw[i], si = sw[i];
                #pragma unroll
                for (int q = 0; q < 8; q++) {
                    int j = j0 + q;
                    float s = (j <= i) ? acc[r][q] * (ci * cw[j] + si * sw[j]) : 0.f;
                    S[i * CHUNK + j] = s;
                }
            }
        }
    }
    __syncthreads();

    // ---- nrm_i = cos_i*(rq_i . K0c) + sin_i*(rq_i . K0s) + sum_{j<=i} S[i][j]
    if (tid < CHUNK) {
        const int i = tid;
        float dc = 0.f, ds = 0.f;
        for (int d = 0; d < DDIM; d++) {
            float q = rqT[d * RQT_STRIDE + i];
            dc += q * K0c[d];
            ds += q * K0s[d];
        }
        float n = cw[i] * dc + sw[i] * ds;
        for (int j = 0; j <= i; j++) n += S[i * CHUNK + j];
        nrm[i] = n;
    }
    __syncthreads();

    // ---- ctx + normalize + store. Each thread: (i, 16 e's), 2 items.
    #pragma unroll
    for (int rep = 0; rep < 2; rep++) {
        const int item = tid + 256 * rep;
        const int i  = item >> 2;
        const int eg = (item & 3) << 4;

        float aC[16], aS[16], aI[16];
        #pragma unroll
        for (int e = 0; e < 16; e++) { aC[e] = 0.f; aS[e] = 0.f; aI[e] = 0.f; }

        for (int d = 0; d < DDIM; d++) {
            float q = rqT[d * RQT_STRIDE + i];
            const float4* pc = reinterpret_cast<const float4*>(&KVc[d * DDIM + eg]);
            const float4* ps = reinterpret_cast<const float4*>(&KVs[d * DDIM + eg]);
            #pragma unroll
            for (int e4 = 0; e4 < 4; e4++) {
                float4 c4v = pc[e4];
                float4 s4v = ps[e4];
                aC[e4 * 4 + 0] += q * c4v.x; aC[e4 * 4 + 1] += q * c4v.y;
                aC[e4 * 4 + 2] += q * c4v.z; aC[e4 * 4 + 3] += q * c4v.w;
                aS[e4 * 4 + 0] += q * s4v.x; aS[e4 * 4 + 1] += q * s4v.y;
                aS[e4 * 4 + 2] += q * s4v.z; aS[e4 * 4 + 3] += q * s4v.w;
            }
        }
        for (int j = 0; j <= i; j++) {
            float s = S[i * CHUNK + j];
            const float4* pv = reinterpret_cast<const float4*>(&vv[j * DDIM + eg]);
            #pragma unroll
            for (int e4 = 0; e4 < 4; e4++) {
                float4 v4 = pv[e4];
                aI[e4 * 4 + 0] += s * v4.x; aI[e4 * 4 + 1] += s * v4.y;
                aI[e4 * 4 + 2] += s * v4.z; aI[e4 * 4 + 3] += s * v4.w;
            }
        }
        float ci = cw[i], si = sw[i];
        float inv = 1.0f / (nrm[i] + 1e-6f);
        float* op = &g_attn[(size_t)(c * CHUNK + i) * EDIM + h * DDIM + eg];
        #pragma unroll
        for (int e = 0; e < 16; e++)
            op[e] = (ci * aC[e] + si * aS[e] + aI[e]) * inv;
    }
}

// ---------------------------------------------------------------------------

static const int SMEM_SUM = (2 * CHUNK * DDIM + 2 * CHUNK) * (int)sizeof(float);
static const int SMEM_OUT = (2 * DDIM * RQT_STRIDE + CHUNK * DDIM + CHUNK * CHUNK +
                             2 * DDIM * DDIM + 2 * DDIM + 3 * CHUNK) * (int)sizeof(float);

extern "C" void kernel_launch(void* const* d_in, const int* in_sizes, int n_in,
                              void* d_out, int out_size) {
    (void)in_sizes; (void)n_in; (void)out_size;
    const float* x    = (const float*)d_in[0];
    const float* Wqkv = (const float*)d_in[1];
    const float* bqkv = (const float*)d_in[2];
    const float* Wout = (const float*)d_in[3];
    const float* bout = (const float*)d_in[4];
    float* out = (float*)d_out;

    float *qkv_ptr, *attn_ptr;
    cudaGetSymbolAddress((void**)&qkv_ptr, g_qkv);
    cudaGetSymbolAddress((void**)&attn_ptr, g_attn);

    cudaFuncSetAttribute(chunk_sum_kernel,
                         cudaFuncAttributeMaxDynamicSharedMemorySize, SMEM_SUM);
    cudaFuncSetAttribute(chunk_out_kernel,
                         cudaFuncAttributeMaxDynamicSharedMemorySize, SMEM_OUT);

    // 1) QKV GEMM: [2048,512] @ [512,1536] + bias
    sgemm_bias<128, 128, 16, 8, 8>
        <<<dim3(E3 / 128, LSEQ / 128), 256>>>(x, Wqkv, bqkv, qkv_ptr, LSEQ, E3, EDIM);

    // 2) Chunked cosformer attention
    chunk_sum_kernel<<<dim3(NCH, HEADS), 256, SMEM_SUM>>>();
    scan_kernel<<<HEADS, 256>>>();
    chunk_out_kernel<<<dim3(NCH, HEADS), 256, SMEM_OUT>>>();

    // 3) Output GEMM: [2048,512] @ [512,512] + bias
    sgemm_bias<128, 64, 16, 8, 4>
        <<<dim3(EDIM / 64, LSEQ / 128), 256>>>(attn_ptr, Wout, bout, out, LSEQ, EDIM, EDIM);
}

// round 3
// speedup vs baseline: 1.2727x; 1.2727x over previous
#include <cuda_runtime.h>
#include <cuda_bf16.h>
#include <cstdint>
#include <cstddef>

// Problem constants
#define LSEQ 2048
#define EDIM 512
#define HEADS 8
#define DDIM 64
#define E3   1536
#define CHUNK 128
#define NCH  16

#define THETA_SCALE 7.66990393942820573e-4f  // (pi/2)/2048

// ---------------- scratch (device globals; no allocs allowed) ----------------
__device__ float g_qkv[LSEQ * E3];
__device__ float g_attn[LSEQ * EDIM];
__device__ float g_ckv[HEADS * NCH * 2 * DDIM * DDIM];
__device__ float g_ck [HEADS * NCH * 2 * DDIM];
__device__ float g_pkv[HEADS * NCH * 2 * DDIM * DDIM];
__device__ float g_pk [HEADS * NCH * 2 * DDIM];

// bf16 split buffers
__device__ __nv_bfloat16 g_xh[LSEQ * EDIM];
__device__ __nv_bfloat16 g_xl[LSEQ * EDIM];
__device__ __nv_bfloat16 g_wqh[E3 * EDIM];   // Wqkv^T  [1536][512]
__device__ __nv_bfloat16 g_wql[E3 * EDIM];
__device__ __nv_bfloat16 g_woh[EDIM * EDIM]; // Wout^T  [512][512]
__device__ __nv_bfloat16 g_wol[EDIM * EDIM];
__device__ __nv_bfloat16 g_ah[LSEQ * EDIM];
__device__ __nv_bfloat16 g_al[LSEQ * EDIM];

// ---------------- low-level helpers (compute_80-era, valid at compute_103) ----
__device__ __forceinline__ uint32_t smem_u32(const void* p) {
    uint32_t a;
    asm("{ .reg .u64 t; cvta.to.shared.u64 t, %1; cvt.u32.u64 %0, t; }"
        : "=r"(a) : "l"(p));
    return a;
}
#define CP_ASYNC16(dst, src) \
    asm volatile("cp.async.cg.shared.global [%0], [%1], 16;" :: "r"(dst), "l"(src))
#define CP_COMMIT() asm volatile("cp.async.commit_group;" ::: "memory")
#define CP_WAIT0()  asm volatile("cp.async.wait_group 0;" ::: "memory")
#define CP_WAIT1()  asm volatile("cp.async.wait_group 1;" ::: "memory")

__device__ __forceinline__ void ldmx4(uint32_t* r, uint32_t addr) {
    asm volatile("ldmatrix.sync.aligned.m8n8.x4.shared.b16 {%0,%1,%2,%3}, [%4];"
                 : "=r"(r[0]), "=r"(r[1]), "=r"(r[2]), "=r"(r[3]) : "r"(addr));
}
__device__ __forceinline__ void mma16816(float* c, const uint32_t* a, const uint32_t* b) {
    asm volatile(
        "mma.sync.aligned.m16n8k16.row.col.f32.bf16.bf16.f32 "
        "{%0,%1,%2,%3}, {%4,%5,%6,%7}, {%8,%9}, {%0,%1,%2,%3};"
        : "+f"(c[0]), "+f"(c[1]), "+f"(c[2]), "+f"(c[3])
        : "r"(a[0]), "r"(a[1]), "r"(a[2]), "r"(a[3]), "r"(b[0]), "r"(b[1]));
}

// ---------------- bf16 split conversion kernels ----------------
__global__ __launch_bounds__(256)
void split_bf16_kernel(const float* __restrict__ src,
                       __nv_bfloat16* __restrict__ hi, __nv_bfloat16* __restrict__ lo, int n) {
    int i = blockIdx.x * 256 + threadIdx.x;
    if (i < n) {
        float a = src[i];
        __nv_bfloat16 h = __float2bfloat16(a);
        hi[i] = h;
        lo[i] = __float2bfloat16(a - __bfloat162float(h));
    }
}

// W[K,N] -> WT hi/lo [N,K]  (tiled transpose)
__global__ __launch_bounds__(256)
void split_bf16_T_kernel(const float* __restrict__ W,
                         __nv_bfloat16* __restrict__ hiT, __nv_bfloat16* __restrict__ loT,
                         int K, int N) {
    __shared__ float t[32][33];
    const int tx = threadIdx.x & 31, ty = threadIdx.x >> 5;  // (32, 8)
    const int n0 = blockIdx.x * 32, k0 = blockIdx.y * 32;
    #pragma unroll
    for (int j = 0; j < 4; j++)
        t[ty + 8 * j][tx] = W[(size_t)(k0 + ty + 8 * j) * N + n0 + tx];
    __syncthreads();
    #pragma unroll
    for (int j = 0; j < 4; j++) {
        float a = t[tx][ty + 8 * j];  // = W[k0+tx][n0+ty+8j]
        __nv_bfloat16 h = __float2bfloat16(a);
        size_t o = (size_t)(n0 + ty + 8 * j) * K + k0 + tx;
        hiT[o] = h;
        loT[o] = __float2bfloat16(a - __bfloat162float(h));
    }
}

// ---------------- mma.sync bf16x3 GEMM: C[M,N] = A @ Bt^T + bias ----------------
// A hi/lo [M,K] row-major; Bt hi/lo [N,K] row-major. K multiple of 32.
// CTA tile 128x128, 8 warps (2x4), warp tile 64x32. K-chunk 32, double buffer.
#define KC 32
#define AST 40   // smem row stride in bf16 elems (80 bytes -> conflict-free ldmatrix)
#define TILE_E (128 * AST)          // 5120 elems per tile
#define BUF_E  (4 * TILE_E)         // Ah, Al, Bh, Bl
#define GSMEM_BYTES (2 * BUF_E * 2) // 81920

__global__ __launch_bounds__(256, 1)
void mma_gemm_kernel(const __nv_bfloat16* __restrict__ Ah, const __nv_bfloat16* __restrict__ Al,
                     const __nv_bfloat16* __restrict__ Bh, const __nv_bfloat16* __restrict__ Bl,
                     const float* __restrict__ bias, float* __restrict__ C,
                     int N, int K) {
    extern __shared__ __nv_bfloat16 smem[];
    const int tid = threadIdx.x;
    const int wid = tid >> 5, lane = tid & 31;
    const int bn0 = blockIdx.x * 128, bm0 = blockIdx.y * 128;
    const int wm = (wid & 1) * 64;   // warp m offset in tile
    const int wn = (wid >> 1) * 32;  // warp n offset in tile

    const uint32_t smb = smem_u32(smem);
    const int NCHK = K / KC;

    float acc[4][4][4];
    #pragma unroll
    for (int mi = 0; mi < 4; mi++)
        #pragma unroll
        for (int nj = 0; nj < 4; nj++)
            #pragma unroll
            for (int r = 0; r < 4; r++) acc[mi][nj][r] = 0.f;

    const __nv_bfloat16* srcs[4] = {Ah, Al, Bh, Bl};
    const int srow[4] = {bm0, bm0, bn0, bn0};

    // issue async loads for chunk c into buffer b
    auto load_chunk = [&](int b, int k0) {
        #pragma unroll
        for (int t = 0; t < 4; t++) {
            const __nv_bfloat16* s = srcs[t];
            uint32_t dbase = smb + (uint32_t)(b * BUF_E + t * TILE_E) * 2u;
            #pragma unroll
            for (int r = 0; r < 2; r++) {
                int item = tid + 256 * r;        // 512 x 16B per tile
                int row = item >> 2, sub = item & 3;
                uint32_t d = dbase + (uint32_t)(row * AST + sub * 8) * 2u;
                const void* g = (const void*)(s + (size_t)(srow[t] + row) * K + k0 + sub * 8);
                CP_ASYNC16(d, g);
            }
        }
        CP_COMMIT();
    };

    load_chunk(0, 0);

    for (int c = 0; c < NCHK; c++) {
        const int b = c & 1;
        if (c + 1 < NCHK) {
            load_chunk(b ^ 1, (c + 1) * KC);
            CP_WAIT1();
        } else {
            CP_WAIT0();
        }
        __syncthreads();

        const uint32_t aBh = smb + (uint32_t)(b * BUF_E) * 2u;
        const uint32_t aBl = aBh + TILE_E * 2u;
        const uint32_t bBh = aBh + 2u * TILE_E * 2u;
        const uint32_t bBl = aBh + 3u * TILE_E * 2u;

        #pragma unroll
        for (int ks = 0; ks < KC; ks += 16) {
            // A fragments: rows m (lane&15), col half (lane>>4)*8
            const int arow = wm + (lane & 15);
            const int acol = ks + ((lane >> 4) << 3);
            uint32_t ah[4][4], al[4][4];
            #pragma unroll
            for (int mi = 0; mi < 4; mi++) {
                uint32_t off = (uint32_t)((arow + mi * 16) * AST + acol) * 2u;
                ldmx4(ah[mi], aBh + off);
                ldmx4(al[mi], aBl + off);
            }
            // B fragments: rows n, blocks: (lane&7) + ((lane&16)?8:0); col ks + ((lane&8)?8:0)
            const int brow = wn + (lane & 7) + ((lane & 16) ? 8 : 0);
            const int bcol = ks + ((lane & 8) ? 8 : 0);
            uint32_t bh[2][4], bl[2][4];
            #pragma unroll
            for (int ni = 0; ni < 2; ni++) {
                uint32_t off = (uint32_t)((brow + ni * 16) * AST + bcol) * 2u;
                ldmx4(bh[ni], bBh + off);
                ldmx4(bl[ni], bBl + off);
            }
            #pragma unroll
            for (int mi = 0; mi < 4; mi++) {
                #pragma unroll
                for (int nj = 0; nj < 4; nj++) {
                    const uint32_t* ph = &bh[nj >> 1][(nj & 1) * 2];
                    const uint32_t* pl = &bl[nj >> 1][(nj & 1) * 2];
                    mma16816(acc[mi][nj], ah[mi], ph);
                    mma16816(acc[mi][nj], ah[mi], pl);
                    mma16816(acc[mi][nj], al[mi], ph);
                }
            }
        }
        __syncthreads();
    }

    // Epilogue: direct fragment stores + bias
    const int r0 = bm0 + wm + (lane >> 2);
    const int c0 = bn0 + wn + (lane & 3) * 2;
    #pragma unroll
    for (int mi = 0; mi < 4; mi++) {
        #pragma unroll
        for (int nj = 0; nj < 4; nj++) {
            int row = r0 + mi * 16;
            int col = c0 + nj * 8;
            float b0 = bias[col], b1 = bias[col + 1];
            float2 v0 = make_float2(acc[mi][nj][0] + b0, acc[mi][nj][1] + b1);
            float2 v1 = make_float2(acc[mi][nj][2] + b0, acc[mi][nj][3] + b1);
            *reinterpret_cast<float2*>(&C[(size_t)row * N + col]) = v0;
            *reinterpret_cast<float2*>(&C[(size_t)(row + 8) * N + col]) = v1;
        }
    }
}

// ---------------------------------------------------------------------------
// Attention kernels (unchanged)
// ---------------------------------------------------------------------------
__global__ __launch_bounds__(256)
void chunk_sum_kernel() {
    extern __shared__ float smf[];
    float* rk = smf;
    float* vv = rk + CHUNK * DDIM;
    float* cw = vv + CHUNK * DDIM;
    float* sw = cw + CHUNK;

    const int c = blockIdx.x, h = blockIdx.y, tid = threadIdx.x;

    for (int t = tid; t < CHUNK * DDIM; t += 256) {
        int i = t >> 6, d = t & 63;
        const float* row = g_qkv + (size_t)(c * CHUNK + i) * E3 + h * DDIM;
        rk[t] = fmaxf(row[EDIM + d], 0.f);
        vv[t] = row[2 * EDIM + d];
    }
    if (tid < CHUNK) {
        float th = (float)(c * CHUNK + tid) * THETA_SCALE;
        cw[tid] = cosf(th);
        sw[tid] = sinf(th);
    }
    __syncthreads();

    const int d  = tid & 63;
    const int eg = (tid >> 6) << 4;
    float aC[16], aS[16];
    #pragma unroll
    for (int e = 0; e < 16; e++) { aC[e] = 0.f; aS[e] = 0.f; }

    for (int i = 0; i < CHUNK; i++) {
        float kd = rk[i * DDIM + d];
        float kc = kd * cw[i];
        float ks = kd * sw[i];
        const float4* vp = reinterpret_cast<const float4*>(&vv[i * DDIM + eg]);
        #pragma unroll
        for (int e4 = 0; e4 < 4; e4++) {
            float4 v4 = vp[e4];
            aC[e4 * 4 + 0] += kc * v4.x; aC[e4 * 4 + 1] += kc * v4.y;
            aC[e4 * 4 + 2] += kc * v4.z; aC[e4 * 4 + 3] += kc * v4.w;
            aS[e4 * 4 + 0] += ks * v4.x; aS[e4 * 4 + 1] += ks * v4.y;
            aS[e4 * 4 + 2] += ks * v4.z; aS[e4 * 4 + 3] += ks * v4.w;
        }
    }

    size_t base = (size_t)(h * NCH + c) * 2 * DDIM * DDIM;
    #pragma unroll
    for (int e = 0; e < 16; e++) {
        g_ckv[base + d * DDIM + eg + e]               = aC[e];
        g_ckv[base + DDIM * DDIM + d * DDIM + eg + e] = aS[e];
    }

    if (tid < DDIM) {
        float sc = 0.f, ss = 0.f;
        for (int i = 0; i < CHUNK; i++) {
            float kd = rk[i * DDIM + tid];
            sc += kd * cw[i];
            ss += kd * sw[i];
        }
        size_t kb = (size_t)(h * NCH + c) * 2 * DDIM;
        g_ck[kb + tid]        = sc;
        g_ck[kb + DDIM + tid] = ss;
    }
}

__global__ __launch_bounds__(256)
void scan_kernel() {
    const int h = blockIdx.x, tid = threadIdx.x;
    const int KVSZ = 2 * DDIM * DDIM;
    for (int idx = tid; idx < KVSZ; idx += 256) {
        float run = 0.f;
        for (int c = 0; c < NCH; c++) {
            size_t off = (size_t)(h * NCH + c) * KVSZ + idx;
            g_pkv[off] = run;
            run += g_ckv[off];
        }
    }
    const int KSZ = 2 * DDIM;
    if (tid < KSZ) {
        float run = 0.f;
        for (int c = 0; c < NCH; c++) {
            size_t off = (size_t)(h * NCH + c) * KSZ + tid;
            g_pk[off] = run;
            run += g_ck[off];
        }
    }
}

#define RQT_STRIDE 132

__global__ __launch_bounds__(256, 1)
void chunk_out_kernel() {
    extern __shared__ float smf[];
    float* rqT = smf;
    float* rkT = rqT + DDIM * RQT_STRIDE;
    float* vv  = rkT + DDIM * RQT_STRIDE;
    float* S   = vv + CHUNK * DDIM;
    float* KVc = S + CHUNK * CHUNK;
    float* KVs = KVc + DDIM * DDIM;
    float* K0c = KVs + DDIM * DDIM;
    float* K0s = K0c + DDIM;
    float* cw  = K0s + DDIM;
    float* sw  = cw + CHUNK;
    float* nrm = sw + CHUNK;

    const int c = blockIdx.x, h = blockIdx.y, tid = threadIdx.x;

    for (int t = tid; t < CHUNK * DDIM; t += 256) {
        int i = t >> 6, d = t & 63;
        const float* row = g_qkv + (size_t)(c * CHUNK + i) * E3 + h * DDIM;
        rqT[d * RQT_STRIDE + i] = fmaxf(row[d], 0.f);
        rkT[d * RQT_STRIDE + i] = fmaxf(row[EDIM + d], 0.f);
        vv[i * DDIM + d]        = row[2 * EDIM + d];
    }
    if (tid < CHUNK) {
        float th = (float)(c * CHUNK + tid) * THETA_SCALE;
        cw[tid] = cosf(th);
        sw[tid] = sinf(th);
    }
    {
        const float* base = g_pkv + (size_t)(h * NCH + c) * 2 * DDIM * DDIM;
        for (int t = tid; t < 2 * DDIM * DDIM; t += 256) {
            if (t < DDIM * DDIM) KVc[t] = base[t];
            else                 KVs[t - DDIM * DDIM] = base[t];
        }
        const float* kb = g_pk + (size_t)(h * NCH + c) * 2 * DDIM;
        if (tid < 2 * DDIM) {
            if (tid < DDIM) K0c[tid] = kb[tid];
            else            K0s[tid - DDIM] = kb[tid];
        }
    }
    __syncthreads();

    {
        const int ti = tid >> 4, tj = tid & 15;
        const int i0 = ti * 8, j0 = tj * 8;
        if (j0 <= i0 + 7) {
            float acc[8][8];
            #pragma unroll
            for (int r = 0; r < 8; r++)
                #pragma unroll
                for (int q = 0; q < 8; q++) acc[r][q] = 0.f;

            for (int d = 0; d < DDIM; d++) {
                float a[8], b[8];
                #pragma unroll
                for (int r = 0; r < 8; r++) a[r] = rqT[d * RQT_STRIDE + i0 + r];
                #pragma unroll
                for (int r = 0; r < 8; r++) b[r] = rkT[d * RQT_STRIDE + j0 + r];
                #pragma unroll
                for (int r = 0; r < 8; r++)
                    #pragma unroll
                    for (int q = 0; q < 8; q++)
                        acc[r][q] += a[r] * b[q];
            }
            #pragma unroll
            for (int r = 0; r < 8; r++) {
                int i = i0 + r;
                float ci = cw[i], si = sw[i];
                #pragma unroll
                for (int q = 0; q < 8; q++) {
                    int j = j0 + q;
                    float s = (j <= i) ? acc[r][q] * (ci * cw[j] + si * sw[j]) : 0.f;
                    S[i * CHUNK + j] = s;
                }
            }
        }
    }
    __syncthreads();

    if (tid < CHUNK) {
        const int i = tid;
        float dc = 0.f, ds = 0.f;
        for (int d = 0; d < DDIM; d++) {
            float q = rqT[d * RQT_STRIDE + i];
            dc += q * K0c[d];
            ds += q * K0s[d];
        }
        float n = cw[i] * dc + sw[i] * ds;
        for (int j = 0; j <= i; j++) n += S[i * CHUNK + j];
        nrm[i] = n;
    }
    __syncthreads();

    #pragma unroll
    for (int rep = 0; rep < 2; rep++) {
        const int item = tid + 256 * rep;
        const int i  = item >> 2;
        const int eg = (item & 3) << 4;

        float aC[16], aS[16], aI[16];
        #pragma unroll
        for (int e = 0; e < 16; e++) { aC[e] = 0.f; aS[e] = 0.f; aI[e] = 0.f; }

        for (int d = 0; d < DDIM; d++) {
            float q = rqT[d * RQT_STRIDE + i];
            const float4* pc = reinterpret_cast<const float4*>(&KVc[d * DDIM + eg]);
            const float4* ps = reinterpret_cast<const float4*>(&KVs[d * DDIM + eg]);
            #pragma unroll
            for (int e4 = 0; e4 < 4; e4++) {
                float4 c4v = pc[e4];
                float4 s4v = ps[e4];
                aC[e4 * 4 + 0] += q * c4v.x; aC[e4 * 4 + 1] += q * c4v.y;
                aC[e4 * 4 + 2] += q * c4v.z; aC[e4 * 4 + 3] += q * c4v.w;
                aS[e4 * 4 + 0] += q * s4v.x; aS[e4 * 4 + 1] += q * s4v.y;
                aS[e4 * 4 + 2] += q * s4v.z; aS[e4 * 4 + 3] += q * s4v.w;
            }
        }
        for (int j = 0; j <= i; j++) {
            float s = S[i * CHUNK + j];
            const float4* pv = reinterpret_cast<const float4*>(&vv[j * DDIM + eg]);
            #pragma unroll
            for (int e4 = 0; e4 < 4; e4++) {
                float4 v4 = pv[e4];
                aI[e4 * 4 + 0] += s * v4.x; aI[e4 * 4 + 1] += s * v4.y;
                aI[e4 * 4 + 2] += s * v4.z; aI[e4 * 4 + 3] += s * v4.w;
            }
        }
        float ci = cw[i], si = sw[i];
        float inv = 1.0f / (nrm[i] + 1e-6f);
        float* op = &g_attn[(size_t)(c * CHUNK + i) * EDIM + h * DDIM + eg];
        #pragma unroll
        for (int e = 0; e < 16; e++)
            op[e] = (ci * aC[e] + si * aS[e] + aI[e]) * inv;
    }
}

// ---------------------------------------------------------------------------

static const int SMEM_SUM = (2 * CHUNK * DDIM + 2 * CHUNK) * (int)sizeof(float);
static const int SMEM_OUT = (2 * DDIM * RQT_STRIDE + CHUNK * DDIM + CHUNK * CHUNK +
                             2 * DDIM * DDIM + 2 * DDIM + 3 * CHUNK) * (int)sizeof(float);

extern "C" void kernel_launch(void* const* d_in, const int* in_sizes, int n_in,
                              void* d_out, int out_size) {
    (void)in_sizes; (void)n_in; (void)out_size;
    const float* x    = (const float*)d_in[0];
    const float* Wqkv = (const float*)d_in[1];
    const float* bqkv = (const float*)d_in[2];
    const float* Wout = (const float*)d_in[3];
    const float* bout = (const float*)d_in[4];
    float* out = (float*)d_out;

    float *qkv_ptr, *attn_ptr;
    cudaGetSymbolAddress((void**)&qkv_ptr, g_qkv);
    cudaGetSymbolAddress((void**)&attn_ptr, g_attn);
    __nv_bfloat16 *xh, *xl, *wqh, *wql, *woh, *wol, *ah, *al;
    cudaGetSymbolAddress((void**)&xh, g_xh);
    cudaGetSymbolAddress((void**)&xl, g_xl);
    cudaGetSymbolAddress((void**)&wqh, g_wqh);
    cudaGetSymbolAddress((void**)&wql, g_wql);
    cudaGetSymbolAddress((void**)&woh, g_woh);
    cudaGetSymbolAddress((void**)&wol, g_wol);
    cudaGetSymbolAddress((void**)&ah, g_ah);
    cudaGetSymbolAddress((void**)&al, g_al);

    cudaFuncSetAttribute(chunk_sum_kernel,
                         cudaFuncAttributeMaxDynamicSharedMemorySize, SMEM_SUM);
    cudaFuncSetAttribute(chunk_out_kernel,
                         cudaFuncAttributeMaxDynamicSharedMemorySize, SMEM_OUT);
    cudaFuncSetAttribute(mma_gemm_kernel,
                         cudaFuncAttributeMaxDynamicSharedMemorySize, GSMEM_BYTES);

    // bf16 splits
    split_bf16_kernel<<<(LSEQ * EDIM + 255) / 256, 256>>>(x, xh, xl, LSEQ * EDIM);
    split_bf16_T_kernel<<<dim3(E3 / 32, EDIM / 32), 256>>>(Wqkv, wqh, wql, EDIM, E3);
    split_bf16_T_kernel<<<dim3(EDIM / 32, EDIM / 32), 256>>>(Wout, woh, wol, EDIM, EDIM);

    // 1) QKV GEMM (mma.sync bf16x3): [2048,512] @ [512,1536] + bias
    mma_gemm_kernel<<<dim3(E3 / 128, LSEQ / 128), 256, GSMEM_BYTES>>>(
        xh, xl, wqh, wql, bqkv, qkv_ptr, E3, EDIM);

    // 2) Chunked cosformer attention
    chunk_sum_kernel<<<dim3(NCH, HEADS), 256, SMEM_SUM>>>();
    scan_kernel<<<HEADS, 256>>>();
    chunk_out_kernel<<<dim3(NCH, HEADS), 256, SMEM_OUT>>>();

    // 3) Output GEMM (mma.sync bf16x3): [2048,512] @ [512,512] + bias
    split_bf16_kernel<<<(LSEQ * EDIM + 255) / 256, 256>>>(attn_ptr, ah, al, LSEQ * EDIM);
    mma_gemm_kernel<<<dim3(EDIM / 128, LSEQ / 128), 256, GSMEM_BYTES>>>(
        ah, al, woh, wol, bout, out, EDIM, EDIM);
}

// round 4
// speedup vs baseline: 2.4897x; 1.9563x over previous
#include <cuda_runtime.h>
#include <cuda_bf16.h>
#include <cstdint>
#include <cstddef>

// Problem constants
#define LSEQ 2048
#define EDIM 512
#define HEADS 8
#define DDIM 64
#define E3   1536
#define CHUNK 128
#define NCH  16

#define THETA_SCALE 7.66990393942820573e-4f  // (pi/2)/2048

// ---------------- scratch (device globals; no allocs allowed) ----------------
__device__ float g_qkv[LSEQ * E3];
__device__ float g_ckv[HEADS * NCH * 2 * DDIM * DDIM];
__device__ float g_ck [HEADS * NCH * 2 * DDIM];
__device__ float g_pkv[HEADS * NCH * 2 * DDIM * DDIM];
__device__ float g_pk [HEADS * NCH * 2 * DDIM];

// bf16 split buffers
__device__ __nv_bfloat16 g_xh[LSEQ * EDIM];
__device__ __nv_bfloat16 g_xl[LSEQ * EDIM];
__device__ __nv_bfloat16 g_wqh[E3 * EDIM];   // Wqkv^T  [1536][512]
__device__ __nv_bfloat16 g_wql[E3 * EDIM];
__device__ __nv_bfloat16 g_woh[EDIM * EDIM]; // Wout^T  [512][512]
__device__ __nv_bfloat16 g_wol[EDIM * EDIM];
__device__ __nv_bfloat16 g_ah[LSEQ * EDIM];  // attention out hi/lo (written by chunk_out)
__device__ __nv_bfloat16 g_al[LSEQ * EDIM];

// ---------------- low-level helpers ----------------
__device__ __forceinline__ uint32_t smem_u32(const void* p) {
    uint32_t a;
    asm("{ .reg .u64 t; cvta.to.shared.u64 t, %1; cvt.u32.u64 %0, t; }"
        : "=r"(a) : "l"(p));
    return a;
}
#define CP_ASYNC16(dst, src) \
    asm volatile("cp.async.cg.shared.global [%0], [%1], 16;" :: "r"(dst), "l"(src))
#define CP_COMMIT() asm volatile("cp.async.commit_group;" ::: "memory")
#define CP_WAIT0()  asm volatile("cp.async.wait_group 0;" ::: "memory")
#define CP_WAIT1()  asm volatile("cp.async.wait_group 1;" ::: "memory")

__device__ __forceinline__ void ldmx4(uint32_t* r, uint32_t addr) {
    asm volatile("ldmatrix.sync.aligned.m8n8.x4.shared.b16 {%0,%1,%2,%3}, [%4];"
                 : "=r"(r[0]), "=r"(r[1]), "=r"(r[2]), "=r"(r[3]) : "r"(addr));
}
__device__ __forceinline__ void mma16816(float* c, const uint32_t* a, const uint32_t* b) {
    asm volatile(
        "mma.sync.aligned.m16n8k16.row.col.f32.bf16.bf16.f32 "
        "{%0,%1,%2,%3}, {%4,%5,%6,%7}, {%8,%9}, {%0,%1,%2,%3};"
        : "+f"(c[0]), "+f"(c[1]), "+f"(c[2]), "+f"(c[3])
        : "r"(a[0]), "r"(a[1]), "r"(a[2]), "r"(a[3]), "r"(b[0]), "r"(b[1]));
}

// ---------------- bf16 split conversion kernels ----------------
__global__ __launch_bounds__(256)
void split_bf16_kernel(const float* __restrict__ src,
                       __nv_bfloat16* __restrict__ hi, __nv_bfloat16* __restrict__ lo, int n) {
    int i = blockIdx.x * 256 + threadIdx.x;
    if (i < n) {
        float a = src[i];
        __nv_bfloat16 h = __float2bfloat16(a);
        hi[i] = h;
        lo[i] = __float2bfloat16(a - __bfloat162float(h));
    }
}

// W[K,N] -> WT hi/lo [N,K]  (tiled transpose)
__global__ __launch_bounds__(256)
void split_bf16_T_kernel(const float* __restrict__ W,
                         __nv_bfloat16* __restrict__ hiT, __nv_bfloat16* __restrict__ loT,
                         int K, int N) {
    __shared__ float t[32][33];
    const int tx = threadIdx.x & 31, ty = threadIdx.x >> 5;  // (32, 8)
    const int n0 = blockIdx.x * 32, k0 = blockIdx.y * 32;
    #pragma unroll
    for (int j = 0; j < 4; j++)
        t[ty + 8 * j][tx] = W[(size_t)(k0 + ty + 8 * j) * N + n0 + tx];
    __syncthreads();
    #pragma unroll
    for (int j = 0; j < 4; j++) {
        float a = t[tx][ty + 8 * j];  // = W[k0+tx][n0+ty+8j]
        __nv_bfloat16 h = __float2bfloat16(a);
        size_t o = (size_t)(n0 + ty + 8 * j) * K + k0 + tx;
        hiT[o] = h;
        loT[o] = __float2bfloat16(a - __bfloat162float(h));
    }
}

// ---------------- mma.sync bf16x3 GEMM (unchanged from R3) ----------------
#define KC 32
#define AST 40
#define TILE_E (128 * AST)
#define BUF_E  (4 * TILE_E)
#define GSMEM_BYTES (2 * BUF_E * 2)

__global__ __launch_bounds__(256, 1)
void mma_gemm_kernel(const __nv_bfloat16* __restrict__ Ah, const __nv_bfloat16* __restrict__ Al,
                     const __nv_bfloat16* __restrict__ Bh, const __nv_bfloat16* __restrict__ Bl,
                     const float* __restrict__ bias, float* __restrict__ C,
                     int N, int K) {
    extern __shared__ __nv_bfloat16 smem[];
    const int tid = threadIdx.x;
    const int wid = tid >> 5, lane = tid & 31;
    const int bn0 = blockIdx.x * 128, bm0 = blockIdx.y * 128;
    const int wm = (wid & 1) * 64;
    const int wn = (wid >> 1) * 32;

    const uint32_t smb = smem_u32(smem);
    const int NCHK = K / KC;

    float acc[4][4][4];
    #pragma unroll
    for (int mi = 0; mi < 4; mi++)
        #pragma unroll
        for (int nj = 0; nj < 4; nj++)
            #pragma unroll
            for (int r = 0; r < 4; r++) acc[mi][nj][r] = 0.f;

    const __nv_bfloat16* srcs[4] = {Ah, Al, Bh, Bl};
    const int srow[4] = {bm0, bm0, bn0, bn0};

    auto load_chunk = [&](int b, int k0) {
        #pragma unroll
        for (int t = 0; t < 4; t++) {
            const __nv_bfloat16* s = srcs[t];
            uint32_t dbase = smb + (uint32_t)(b * BUF_E + t * TILE_E) * 2u;
            #pragma unroll
            for (int r = 0; r < 2; r++) {
                int item = tid + 256 * r;
                int row = item >> 2, sub = item & 3;
                uint32_t d = dbase + (uint32_t)(row * AST + sub * 8) * 2u;
                const void* g = (const void*)(s + (size_t)(srow[t] + row) * K + k0 + sub * 8);
                CP_ASYNC16(d, g);
            }
        }
        CP_COMMIT();
    };

    load_chunk(0, 0);

    for (int c = 0; c < NCHK; c++) {
        const int b = c & 1;
        if (c + 1 < NCHK) {
            load_chunk(b ^ 1, (c + 1) * KC);
            CP_WAIT1();
        } else {
            CP_WAIT0();
        }
        __syncthreads();

        const uint32_t aBh = smb + (uint32_t)(b * BUF_E) * 2u;
        const uint32_t aBl = aBh + TILE_E * 2u;
        const uint32_t bBh = aBh + 2u * TILE_E * 2u;
        const uint32_t bBl = aBh + 3u * TILE_E * 2u;

        #pragma unroll
        for (int ks = 0; ks < KC; ks += 16) {
            const int arow = wm + (lane & 15);
            const int acol = ks + ((lane >> 4) << 3);
            uint32_t ah[4][4], al[4][4];
            #pragma unroll
            for (int mi = 0; mi < 4; mi++) {
                uint32_t off = (uint32_t)((arow + mi * 16) * AST + acol) * 2u;
                ldmx4(ah[mi], aBh + off);
                ldmx4(al[mi], aBl + off);
            }
            const int brow = wn + (lane & 7) + ((lane & 16) ? 8 : 0);
            const int bcol = ks + ((lane & 8) ? 8 : 0);
            uint32_t bh[2][4], bl[2][4];
            #pragma unroll
            for (int ni = 0; ni < 2; ni++) {
                uint32_t off = (uint32_t)((brow + ni * 16) * AST + bcol) * 2u;
                ldmx4(bh[ni], bBh + off);
                ldmx4(bl[ni], bBl + off);
            }
            #pragma unroll
            for (int mi = 0; mi < 4; mi++) {
                #pragma unroll
                for (int nj = 0; nj < 4; nj++) {
                    const uint32_t* ph = &bh[nj >> 1][(nj & 1) * 2];
                    const uint32_t* pl = &bl[nj >> 1][(nj & 1) * 2];
                    mma16816(acc[mi][nj], ah[mi], ph);
                    mma16816(acc[mi][nj], ah[mi], pl);
                    mma16816(acc[mi][nj], al[mi], ph);
                }
            }
        }
        __syncthreads();
    }

    const int r0 = bm0 + wm + (lane >> 2);
    const int c0 = bn0 + wn + (lane & 3) * 2;
    #pragma unroll
    for (int mi = 0; mi < 4; mi++) {
        #pragma unroll
        for (int nj = 0; nj < 4; nj++) {
            int row = r0 + mi * 16;
            int col = c0 + nj * 8;
            float b0 = bias[col], b1 = bias[col + 1];
            float2 v0 = make_float2(acc[mi][nj][0] + b0, acc[mi][nj][1] + b1);
            float2 v1 = make_float2(acc[mi][nj][2] + b0, acc[mi][nj][3] + b1);
            *reinterpret_cast<float2*>(&C[(size_t)row * N + col]) = v0;
            *reinterpret_cast<float2*>(&C[(size_t)(row + 8) * N + col]) = v1;
        }
    }
}

// ---------------------------------------------------------------------------
// chunk_sum: per-chunk KV / K sums (unchanged)
// ---------------------------------------------------------------------------
__global__ __launch_bounds__(256)
void chunk_sum_kernel() {
    extern __shared__ float smf[];
    float* rk = smf;
    float* vv = rk + CHUNK * DDIM;
    float* cw = vv + CHUNK * DDIM;
    float* sw = cw + CHUNK;

    const int c = blockIdx.x, h = blockIdx.y, tid = threadIdx.x;

    for (int t = tid; t < CHUNK * DDIM; t += 256) {
        int i = t >> 6, d = t & 63;
        const float* row = g_qkv + (size_t)(c * CHUNK + i) * E3 + h * DDIM;
        rk[t] = fmaxf(row[EDIM + d], 0.f);
        vv[t] = row[2 * EDIM + d];
    }
    if (tid < CHUNK) {
        float th = (float)(c * CHUNK + tid) * THETA_SCALE;
        cw[tid] = cosf(th);
        sw[tid] = sinf(th);
    }
    __syncthreads();

    const int d  = tid & 63;
    const int eg = (tid >> 6) << 4;
    float aC[16], aS[16];
    #pragma unroll
    for (int e = 0; e < 16; e++) { aC[e] = 0.f; aS[e] = 0.f; }

    for (int i = 0; i < CHUNK; i++) {
        float kd = rk[i * DDIM + d];
        float kc = kd * cw[i];
        float ks = kd * sw[i];
        const float4* vp = reinterpret_cast<const float4*>(&vv[i * DDIM + eg]);
        #pragma unroll
        for (int e4 = 0; e4 < 4; e4++) {
            float4 v4 = vp[e4];
            aC[e4 * 4 + 0] += kc * v4.x; aC[e4 * 4 + 1] += kc * v4.y;
            aC[e4 * 4 + 2] += kc * v4.z; aC[e4 * 4 + 3] += kc * v4.w;
            aS[e4 * 4 + 0] += ks * v4.x; aS[e4 * 4 + 1] += ks * v4.y;
            aS[e4 * 4 + 2] += ks * v4.z; aS[e4 * 4 + 3] += ks * v4.w;
        }
    }

    size_t base = (size_t)(h * NCH + c) * 2 * DDIM * DDIM;
    #pragma unroll
    for (int e = 0; e < 16; e++) {
        g_ckv[base + d * DDIM + eg + e]               = aC[e];
        g_ckv[base + DDIM * DDIM + d * DDIM + eg + e] = aS[e];
    }

    if (tid < DDIM) {
        float sc = 0.f, ss = 0.f;
        for (int i = 0; i < CHUNK; i++) {
            float kd = rk[i * DDIM + tid];
            sc += kd * cw[i];
            ss += kd * sw[i];
        }
        size_t kb = (size_t)(h * NCH + c) * 2 * DDIM;
        g_ck[kb + tid]        = sc;
        g_ck[kb + DDIM + tid] = ss;
    }
}

// ---------------------------------------------------------------------------
// scan: exclusive prefix over 16 chunks — prefetch all 16 into regs (MLP)
// ---------------------------------------------------------------------------
__global__ __launch_bounds__(256)
void scan_kernel() {
    const int h = blockIdx.x, tid = threadIdx.x;
    const int KVSZ = 2 * DDIM * DDIM;  // 8192
    for (int idx = tid; idx < KVSZ; idx += 256) {
        float v[NCH];
        #pragma unroll
        for (int c = 0; c < NCH; c++)
            v[c] = g_ckv[(size_t)(h * NCH + c) * KVSZ + idx];
        float run = 0.f;
        #pragma unroll
        for (int c = 0; c < NCH; c++) {
            g_pkv[(size_t)(h * NCH + c) * KVSZ + idx] = run;
            run += v[c];
        }
    }
    const int KSZ = 2 * DDIM;  // 128
    if (tid < KSZ) {
        float v[NCH];
        #pragma unroll
        for (int c = 0; c < NCH; c++)
            v[c] = g_ck[(size_t)(h * NCH + c) * KSZ + tid];
        float run = 0.f;
        #pragma unroll
        for (int c = 0; c < NCH; c++) {
            g_pk[(size_t)(h * NCH + c) * KSZ + tid] = run;
            run += v[c];
        }
    }
}

// ---------------------------------------------------------------------------
// chunk_out: register-tiled, predicated-causal, fused bf16-split output.
// grid (NCH, HEADS), 256 threads.
// ---------------------------------------------------------------------------
#define RQT_STRIDE 132
#define S_STRIDE   130

__global__ __launch_bounds__(256, 1)
void chunk_out_kernel() {
    extern __shared__ float smf[];
    float* rqT = smf;                       // [64][132]
    float* rkT = rqT + DDIM * RQT_STRIDE;   // [64][132]
    float* vv  = rkT + DDIM * RQT_STRIDE;   // [128][64]
    float* S   = vv + CHUNK * DDIM;         // [128][130] (valid only j<=i)
    float* KVc = S + CHUNK * S_STRIDE;      // [64][64]
    float* KVs = KVc + DDIM * DDIM;         // [64][64]
    float* K0c = KVs + DDIM * DDIM;         // [64]
    float* K0s = K0c + DDIM;                // [64]
    float* cw  = K0s + DDIM;                // [128]
    float* sw  = cw + CHUNK;                // [128]
    float* nA  = sw + CHUNK;                // [128]
    float* nB  = nA + CHUNK;                // [128]

    const int c = blockIdx.x, h = blockIdx.y, tid = threadIdx.x;

    // ---- load Q/K/V chunk + prefix states
    for (int t = tid; t < CHUNK * DDIM; t += 256) {
        int i = t >> 6, d = t & 63;
        const float* row = g_qkv + (size_t)(c * CHUNK + i) * E3 + h * DDIM;
        rqT[d * RQT_STRIDE + i] = fmaxf(row[d], 0.f);
        rkT[d * RQT_STRIDE + i] = fmaxf(row[EDIM + d], 0.f);
        vv[i * DDIM + d]        = row[2 * EDIM + d];
    }
    if (tid < CHUNK) {
        float th = (float)(c * CHUNK + tid) * THETA_SCALE;
        cw[tid] = cosf(th);
        sw[tid] = sinf(th);
    }
    {
        const float* base = g_pkv + (size_t)(h * NCH + c) * 2 * DDIM * DDIM;
        for (int t = tid; t < 2 * DDIM * DDIM; t += 256) {
            if (t < DDIM * DDIM) KVc[t] = base[t];
            else                 KVs[t - DDIM * DDIM] = base[t];
        }
        const float* kb = g_pk + (size_t)(h * NCH + c) * 2 * DDIM;
        if (tid < 2 * DDIM) {
            if (tid < DDIM) K0c[tid] = kb[tid];
            else            K0s[tid - DDIM] = kb[tid];
        }
    }
    __syncthreads();

    // ---- phase 1: S[i][j] = (rq_i . rk_j) * cos(ti - tj), stored only j<=i
    {
        const int ti = tid >> 4, tj = tid & 15;
        const int i0 = ti * 8, j0 = tj * 8;
        if (j0 <= i0 + 7) {
            float acc[8][8];
            #pragma unroll
            for (int r = 0; r < 8; r++)
                #pragma unroll
                for (int q = 0; q < 8; q++) acc[r][q] = 0.f;

            for (int d = 0; d < DDIM; d++) {
                float a[8], b[8];
                #pragma unroll
                for (int r = 0; r < 8; r++) a[r] = rqT[d * RQT_STRIDE + i0 + r];
                #pragma unroll
                for (int r = 0; r < 8; r++) b[r] = rkT[d * RQT_STRIDE + j0 + r];
                #pragma unroll
                for (int r = 0; r < 8; r++)
                    #pragma unroll
                    for (int q = 0; q < 8; q++)
                        acc[r][q] += a[r] * b[q];
            }
            #pragma unroll
            for (int r = 0; r < 8; r++) {
                int i = i0 + r;
                float ci = cw[i], si = sw[i];
                #pragma unroll
                for (int q = 0; q < 8; q++) {
                    int j = j0 + q;
                    if (j <= i)
                        S[i * S_STRIDE + j] = acc[r][q] * (ci * cw[j] + si * sw[j]);
                }
            }
        }
    }
    __syncthreads();

    // ---- phase 2: nrm split across 256 threads
    if (tid < CHUNK) {
        const int i = tid;
        float dc = 0.f, ds = 0.f;
        for (int d = 0; d < DDIM; d++) {
            float q = rqT[d * RQT_STRIDE + i];
            dc += q * K0c[d];
            ds += q * K0s[d];
        }
        float n = cw[i] * dc + sw[i] * ds;
        int jend = (i < 63) ? i : 63;
        for (int j = 0; j <= jend; j++) n += S[i * S_STRIDE + j];
        nA[i] = n;
    } else {
        const int i = tid - CHUNK;
        float n = 0.f;
        for (int j = 64; j <= i; j++) n += S[i * S_STRIDE + j];
        nB[i] = n;
    }
    __syncthreads();

    // ---- phase 3: register-tiled ctx (4 rows x 8 cols per thread)
    const int tx = tid & 7, ty = tid >> 3;
    const int e0 = tx * 8, i0 = ty * 4;

    float tC[4][8], tS[4][8], tI[4][8];
    #pragma unroll
    for (int r = 0; r < 4; r++)
        #pragma unroll
        for (int e = 0; e < 8; e++) { tC[r][e] = 0.f; tS[r][e] = 0.f; tI[r][e] = 0.f; }

    // Q @ KVc and Q @ KVs  (K = 64)
    for (int d = 0; d < DDIM; d++) {
        float4 q4 = *reinterpret_cast<const float4*>(&rqT[d * RQT_STRIDE + i0]);
        float qr[4] = {q4.x, q4.y, q4.z, q4.w};
        float4 c0 = *reinterpret_cast<const float4*>(&KVc[d * DDIM + e0]);
        float4 c1 = *reinterpret_cast<const float4*>(&KVc[d * DDIM + e0 + 4]);
        float4 s0 = *reinterpret_cast<const float4*>(&KVs[d * DDIM + e0]);
        float4 s1 = *reinterpret_cast<const float4*>(&KVs[d * DDIM + e0 + 4]);
        float cv[8] = {c0.x, c0.y, c0.z, c0.w, c1.x, c1.y, c1.z, c1.w};
        float sv[8] = {s0.x, s0.y, s0.z, s0.w, s1.x, s1.y, s1.z, s1.w};
        #pragma unroll
        for (int r = 0; r < 4; r++)
            #pragma unroll
            for (int e = 0; e < 8; e++) {
                tC[r][e] += qr[r] * cv[e];
                tS[r][e] += qr[r] * sv[e];
            }
    }

    // S @ V causal: full-valid region j = 0..i0
    for (int j = 0; j <= i0; j++) {
        float sr[4];
        #pragma unroll
        for (int r = 0; r < 4; r++) sr[r] = S[(i0 + r) * S_STRIDE + j];
        float4 v0 = *reinterpret_cast<const float4*>(&vv[j * DDIM + e0]);
        float4 v1 = *reinterpret_cast<const float4*>(&vv[j * DDIM + e0 + 4]);
        float ve[8] = {v0.x, v0.y, v0.z, v0.w, v1.x, v1.y, v1.z, v1.w};
        #pragma unroll
        for (int r = 0; r < 4; r++)
            #pragma unroll
            for (int e = 0; e < 8; e++)
                tI[r][e] += sr[r] * ve[e];
    }
    // tail j = i0+1..i0+3 with per-row predication
    #pragma unroll
    for (int dt = 1; dt <= 3; dt++) {
        const int j = i0 + dt;
        float sr[4];
        #pragma unroll
        for (int r = 0; r < 4; r++) {
            float raw = S[(i0 + r) * S_STRIDE + j];
            sr[r] = (dt <= r) ? raw : 0.f;
        }
        float4 v0 = *reinterpret_cast<const float4*>(&vv[j * DDIM + e0]);
        float4 v1 = *reinterpret_cast<const float4*>(&vv[j * DDIM + e0 + 4]);
        float ve[8] = {v0.x, v0.y, v0.z, v0.w, v1.x, v1.y, v1.z, v1.w};
        #pragma unroll
        for (int r = 0; r < 4; r++)
            #pragma unroll
            for (int e = 0; e < 8; e++)
                tI[r][e] += sr[r] * ve[e];
    }

    // ---- epilogue: combine, normalize, bf16 hi/lo split, store
    #pragma unroll
    for (int r = 0; r < 4; r++) {
        const int i = i0 + r;
        float ci = cw[i], si = sw[i];
        float inv = 1.0f / (nA[i] + nB[i] + 1e-6f);
        uint32_t ph[4], pl[4];
        #pragma unroll
        for (int e2 = 0; e2 < 4; e2++) {
            float v0 = (ci * tC[r][e2 * 2 + 0] + si * tS[r][e2 * 2 + 0] + tI[r][e2 * 2 + 0]) * inv;
            float v1 = (ci * tC[r][e2 * 2 + 1] + si * tS[r][e2 * 2 + 1] + tI[r][e2 * 2 + 1]) * inv;
            __nv_bfloat16 h0 = __float2bfloat16(v0);
            __nv_bfloat16 h1 = __float2bfloat16(v1);
            __nv_bfloat16 l0 = __float2bfloat16(v0 - __bfloat162float(h0));
            __nv_bfloat16 l1 = __float2bfloat16(v1 - __bfloat162float(h1));
            ph[e2] = (uint32_t)__bfloat16_as_ushort(h0) |
                     ((uint32_t)__bfloat16_as_ushort(h1) << 16);
            pl[e2] = (uint32_t)__bfloat16_as_ushort(l0) |
                     ((uint32_t)__bfloat16_as_ushort(l1) << 16);
        }
        size_t base = (size_t)(c * CHUNK + i) * EDIM + h * DDIM + e0;
        *reinterpret_cast<uint4*>(&g_ah[base]) = make_uint4(ph[0], ph[1], ph[2], ph[3]);
        *reinterpret_cast<uint4*>(&g_al[base]) = make_uint4(pl[0], pl[1], pl[2], pl[3]);
    }
}

// ---------------------------------------------------------------------------

static const int SMEM_SUM = (2 * CHUNK * DDIM + 2 * CHUNK) * (int)sizeof(float);
static const int SMEM_OUT = (2 * DDIM * RQT_STRIDE + CHUNK * DDIM + CHUNK * S_STRIDE +
                             2 * DDIM * DDIM + 2 * DDIM + 4 * CHUNK) * (int)sizeof(float);

extern "C" void kernel_launch(void* const* d_in, const int* in_sizes, int n_in,
                              void* d_out, int out_size) {
    (void)in_sizes; (void)n_in; (void)out_size;
    const float* x    = (const float*)d_in[0];
    const float* Wqkv = (const float*)d_in[1];
    const float* bqkv = (const float*)d_in[2];
    const float* Wout = (const float*)d_in[3];
    const float* bout = (const float*)d_in[4];
    float* out = (float*)d_out;

    float* qkv_ptr;
    cudaGetSymbolAddress((void**)&qkv_ptr, g_qkv);
    __nv_bfloat16 *xh, *xl, *wqh, *wql, *woh, *wol, *ah, *al;
    cudaGetSymbolAddress((void**)&xh, g_xh);
    cudaGetSymbolAddress((void**)&xl, g_xl);
    cudaGetSymbolAddress((void**)&wqh, g_wqh);
    cudaGetSymbolAddress((void**)&wql, g_wql);
    cudaGetSymbolAddress((void**)&woh, g_woh);
    cudaGetSymbolAddress((void**)&wol, g_wol);
    cudaGetSymbolAddress((void**)&ah, g_ah);
    cudaGetSymbolAddress((void**)&al, g_al);

    cudaFuncSetAttribute(chunk_sum_kernel,
                         cudaFuncAttributeMaxDynamicSharedMemorySize, SMEM_SUM);
    cudaFuncSetAttribute(chunk_out_kernel,
                         cudaFuncAttributeMaxDynamicSharedMemorySize, SMEM_OUT);
    cudaFuncSetAttribute(mma_gemm_kernel,
                         cudaFuncAttributeMaxDynamicSharedMemorySize, GSMEM_BYTES);

    // bf16 splits (inputs)
    split_bf16_kernel<<<(LSEQ * EDIM + 255) / 256, 256>>>(x, xh, xl, LSEQ * EDIM);
    split_bf16_T_kernel<<<dim3(E3 / 32, EDIM / 32), 256>>>(Wqkv, wqh, wql, EDIM, E3);
    split_bf16_T_kernel<<<dim3(EDIM / 32, EDIM / 32), 256>>>(Wout, woh, wol, EDIM, EDIM);

    // 1) QKV GEMM
    mma_gemm_kernel<<<dim3(E3 / 128, LSEQ / 128), 256, GSMEM_BYTES>>>(
        xh, xl, wqh, wql, bqkv, qkv_ptr, E3, EDIM);

    // 2) Chunked cosformer attention (chunk_out writes bf16 hi/lo directly)
    chunk_sum_kernel<<<dim3(NCH, HEADS), 256, SMEM_SUM>>>();
    scan_kernel<<<HEADS, 256>>>();
    chunk_out_kernel<<<dim3(NCH, HEADS), 256, SMEM_OUT>>>();

    // 3) Output GEMM
    mma_gemm_kernel<<<dim3(EDIM / 128, LSEQ / 128), 256, GSMEM_BYTES>>>(
        ah, al, woh, wol, bout, out, EDIM, EDIM);
}

// round 5
// speedup vs baseline: 2.6397x; 1.0602x over previous
#include <cuda_runtime.h>
#include <cuda_bf16.h>
#include <cstdint>
#include <cstddef>

// Problem constants
#define LSEQ 2048
#define EDIM 512
#define HEADS 8
#define DDIM 64
#define E3   1536
#define CHUNK 128
#define NCH  16

#define THETA_SCALE 7.66990393942820573e-4f  // (pi/2)/2048

// ---------------- scratch (device globals; no allocs allowed) ----------------
__device__ float g_qkv[LSEQ * E3];
__device__ float g_ckv[HEADS * NCH * 2 * DDIM * DDIM];
__device__ float g_ck [HEADS * NCH * 2 * DDIM];
__device__ float g_pkv[HEADS * NCH * 2 * DDIM * DDIM];
__device__ float g_pk [HEADS * NCH * 2 * DDIM];

// bf16 split buffers
__device__ __nv_bfloat16 g_xh[LSEQ * EDIM];
__device__ __nv_bfloat16 g_xl[LSEQ * EDIM];
__device__ __nv_bfloat16 g_wqh[E3 * EDIM];   // Wqkv^T  [1536][512]
__device__ __nv_bfloat16 g_wql[E3 * EDIM];
__device__ __nv_bfloat16 g_woh[EDIM * EDIM]; // Wout^T  [512][512]
__device__ __nv_bfloat16 g_wol[EDIM * EDIM];
__device__ __nv_bfloat16 g_ah[LSEQ * EDIM];  // attention out hi/lo
__device__ __nv_bfloat16 g_al[LSEQ * EDIM];

// ---------------- low-level helpers ----------------
__device__ __forceinline__ uint32_t smem_u32(const void* p) {
    uint32_t a;
    asm("{ .reg .u64 t; cvta.to.shared.u64 t, %1; cvt.u32.u64 %0, t; }"
        : "=r"(a) : "l"(p));
    return a;
}
#define CP_ASYNC16(dst, src) \
    asm volatile("cp.async.cg.shared.global [%0], [%1], 16;" :: "r"(dst), "l"(src))
#define CP_COMMIT() asm volatile("cp.async.commit_group;" ::: "memory")
#define CP_WAIT0()  asm volatile("cp.async.wait_group 0;" ::: "memory")
#define CP_WAIT1()  asm volatile("cp.async.wait_group 1;" ::: "memory")

__device__ __forceinline__ void ldmx4(uint32_t* r, uint32_t addr) {
    asm volatile("ldmatrix.sync.aligned.m8n8.x4.shared.b16 {%0,%1,%2,%3}, [%4];"
                 : "=r"(r[0]), "=r"(r[1]), "=r"(r[2]), "=r"(r[3]) : "r"(addr));
}
__device__ __forceinline__ void mma16816(float* c, const uint32_t* a, const uint32_t* b) {
    asm volatile(
        "mma.sync.aligned.m16n8k16.row.col.f32.bf16.bf16.f32 "
        "{%0,%1,%2,%3}, {%4,%5,%6,%7}, {%8,%9}, {%0,%1,%2,%3};"
        : "+f"(c[0]), "+f"(c[1]), "+f"(c[2]), "+f"(c[3])
        : "r"(a[0]), "r"(a[1]), "r"(a[2]), "r"(a[3]), "r"(b[0]), "r"(b[1]));
}

// ---------------- bf16 split conversion kernels ----------------
__global__ __launch_bounds__(256)
void split_bf16_kernel(const float* __restrict__ src,
                       __nv_bfloat16* __restrict__ hi, __nv_bfloat16* __restrict__ lo, int n) {
    int i = blockIdx.x * 256 + threadIdx.x;
    if (i < n) {
        float a = src[i];
        __nv_bfloat16 h = __float2bfloat16(a);
        hi[i] = h;
        lo[i] = __float2bfloat16(a - __bfloat162float(h));
    }
}

// W[K,N] -> WT hi/lo [N,K]  (tiled transpose)
__global__ __launch_bounds__(256)
void split_bf16_T_kernel(const float* __restrict__ W,
                         __nv_bfloat16* __restrict__ hiT, __nv_bfloat16* __restrict__ loT,
                         int K, int N) {
    __shared__ float t[32][33];
    const int tx = threadIdx.x & 31, ty = threadIdx.x >> 5;  // (32, 8)
    const int n0 = blockIdx.x * 32, k0 = blockIdx.y * 32;
    #pragma unroll
    for (int j = 0; j < 4; j++)
        t[ty + 8 * j][tx] = W[(size_t)(k0 + ty + 8 * j) * N + n0 + tx];
    __syncthreads();
    #pragma unroll
    for (int j = 0; j < 4; j++) {
        float a = t[tx][ty + 8 * j];  // = W[k0+tx][n0+ty+8j]
        __nv_bfloat16 h = __float2bfloat16(a);
        size_t o = (size_t)(n0 + ty + 8 * j) * K + k0 + tx;
        hiT[o] = h;
        loT[o] = __float2bfloat16(a - __bfloat162float(h));
    }
}

// ---------------- mma.sync bf16x3 GEMM: C[M,N] = A @ Bt^T + bias --------------
// Templated on BM (CTA tile rows). BN = 128 fixed. 8 warps as 2x4:
// warp tile (BM/2) x 32. K-chunk 32, double-buffered cp.async.
#define KC 32
#define AST 40   // smem row stride in bf16 elems

template<int BM>
__global__ __launch_bounds__(256, 2)
void mma_gemm_kernel(const __nv_bfloat16* __restrict__ Ah, const __nv_bfloat16* __restrict__ Al,
                     const __nv_bfloat16* __restrict__ Bh, const __nv_bfloat16* __restrict__ Bl,
                     const float* __restrict__ bias, float* __restrict__ C,
                     int N, int K) {
    constexpr int MI = BM / 32;                 // m16-fragments per warp
    constexpr int TILE_A = BM * AST;            // elems
    constexpr int TILE_B = 128 * AST;
    constexpr int BUF_E  = 2 * TILE_A + 2 * TILE_B;

    extern __shared__ __nv_bfloat16 smem[];
    const int tid = threadIdx.x;
    const int wid = tid >> 5, lane = tid & 31;
    const int bn0 = blockIdx.x * 128, bm0 = blockIdx.y * BM;
    const int wm = (wid & 1) * (BM / 2);
    const int wn = (wid >> 1) * 32;

    const uint32_t smb = smem_u32(smem);
    const int NCHK = K / KC;

    float acc[MI][4][4];
    #pragma unroll
    for (int mi = 0; mi < MI; mi++)
        #pragma unroll
        for (int nj = 0; nj < 4; nj++)
            #pragma unroll
            for (int r = 0; r < 4; r++) acc[mi][nj][r] = 0.f;

    // tile layout in each buffer: Ah | Al | Bh | Bl
    const __nv_bfloat16* srcs[4] = {Ah, Al, Bh, Bl};
    const int  srow[4] = {bm0, bm0, bn0, bn0};
    const int  titem[4] = {BM * KC / 8, BM * KC / 8, 128 * KC / 8, 128 * KC / 8};
    const uint32_t toff[4] = {0u, (uint32_t)TILE_A, (uint32_t)(2 * TILE_A),
                              (uint32_t)(2 * TILE_A + TILE_B)};

    auto load_chunk = [&](int b, int k0) {
        #pragma unroll
        for (int t = 0; t < 4; t++) {
            const __nv_bfloat16* s = srcs[t];
            uint32_t dbase = smb + (uint32_t)(b * BUF_E + toff[t]) * 2u;
            const int nit = titem[t];
            for (int item = tid; item < nit; item += 256) {
                int row = item >> 2, sub = item & 3;
                uint32_t d = dbase + (uint32_t)(row * AST + sub * 8) * 2u;
                const void* g = (const void*)(s + (size_t)(srow[t] + row) * K + k0 + sub * 8);
                CP_ASYNC16(d, g);
            }
        }
        CP_COMMIT();
    };

    load_chunk(0, 0);

    for (int c = 0; c < NCHK; c++) {
        const int b = c & 1;
        if (c + 1 < NCHK) {
            load_chunk(b ^ 1, (c + 1) * KC);
            CP_WAIT1();
        } else {
            CP_WAIT0();
        }
        __syncthreads();

        const uint32_t aBh = smb + (uint32_t)(b * BUF_E) * 2u;
        const uint32_t aBl = aBh + (uint32_t)TILE_A * 2u;
        const uint32_t bBh = aBh + (uint32_t)(2 * TILE_A) * 2u;
        const uint32_t bBl = bBh + (uint32_t)TILE_B * 2u;

        #pragma unroll
        for (int ks = 0; ks < KC; ks += 16) {
            const int arow = wm + (lane & 15);
            const int acol = ks + ((lane >> 4) << 3);
            uint32_t ah[MI][4], al[MI][4];
            #pragma unroll
            for (int mi = 0; mi < MI; mi++) {
                uint32_t off = (uint32_t)((arow + mi * 16) * AST + acol) * 2u;
                ldmx4(ah[mi], aBh + off);
                ldmx4(al[mi], aBl + off);
            }
            const int brow = wn + (lane & 7) + ((lane & 16) ? 8 : 0);
            const int bcol = ks + ((lane & 8) ? 8 : 0);
            uint32_t bh[2][4], bl[2][4];
            #pragma unroll
            for (int ni = 0; ni < 2; ni++) {
                uint32_t off = (uint32_t)((brow + ni * 16) * AST + bcol) * 2u;
                ldmx4(bh[ni], bBh + off);
                ldmx4(bl[ni], bBl + off);
            }
            #pragma unroll
            for (int mi = 0; mi < MI; mi++) {
                #pragma unroll
                for (int nj = 0; nj < 4; nj++) {
                    const uint32_t* ph = &bh[nj >> 1][(nj & 1) * 2];
                    const uint32_t* pl = &bl[nj >> 1][(nj & 1) * 2];
                    mma16816(acc[mi][nj], ah[mi], ph);
                    mma16816(acc[mi][nj], ah[mi], pl);
                    mma16816(acc[mi][nj], al[mi], ph);
                }
            }
        }
        __syncthreads();
    }

    const int r0 = bm0 + wm + (lane >> 2);
    const int c0 = bn0 + wn + (lane & 3) * 2;
    #pragma unroll
    for (int mi = 0; mi < MI; mi++) {
        #pragma unroll
        for (int nj = 0; nj < 4; nj++) {
            int row = r0 + mi * 16;
            int col = c0 + nj * 8;
            float b0 = bias[col], b1 = bias[col + 1];
            float2 v0 = make_float2(acc[mi][nj][0] + b0, acc[mi][nj][1] + b1);
            float2 v1 = make_float2(acc[mi][nj][2] + b0, acc[mi][nj][3] + b1);
            *reinterpret_cast<float2*>(&C[(size_t)row * N + col]) = v0;
            *reinterpret_cast<float2*>(&C[(size_t)(row + 8) * N + col]) = v1;
        }
    }
}

// smem byte sizes per instantiation
#define GSMEM_128 (2 * (2 * 128 * AST + 2 * 128 * AST) * 2)   // 81920
#define GSMEM_64  (2 * (2 * 64 * AST + 2 * 128 * AST) * 2)    // 61440

// ---------------------------------------------------------------------------
// chunk_sum: per-chunk KV / K sums
// ---------------------------------------------------------------------------
__global__ __launch_bounds__(256)
void chunk_sum_kernel() {
    extern __shared__ float smf[];
    float* rk = smf;
    float* vv = rk + CHUNK * DDIM;
    float* cw = vv + CHUNK * DDIM;
    float* sw = cw + CHUNK;

    const int c = blockIdx.x, h = blockIdx.y, tid = threadIdx.x;

    for (int t = tid; t < CHUNK * DDIM; t += 256) {
        int i = t >> 6, d = t & 63;
        const float* row = g_qkv + (size_t)(c * CHUNK + i) * E3 + h * DDIM;
        rk[t] = fmaxf(row[EDIM + d], 0.f);
        vv[t] = row[2 * EDIM + d];
    }
    if (tid < CHUNK) {
        float th = (float)(c * CHUNK + tid) * THETA_SCALE;
        cw[tid] = cosf(th);
        sw[tid] = sinf(th);
    }
    __syncthreads();

    const int d  = tid & 63;
    const int eg = (tid >> 6) << 4;
    float aC[16], aS[16];
    #pragma unroll
    for (int e = 0; e < 16; e++) { aC[e] = 0.f; aS[e] = 0.f; }

    for (int i = 0; i < CHUNK; i++) {
        float kd = rk[i * DDIM + d];
        float kc = kd * cw[i];
        float ks = kd * sw[i];
        const float4* vp = reinterpret_cast<const float4*>(&vv[i * DDIM + eg]);
        #pragma unroll
        for (int e4 = 0; e4 < 4; e4++) {
            float4 v4 = vp[e4];
            aC[e4 * 4 + 0] += kc * v4.x; aC[e4 * 4 + 1] += kc * v4.y;
            aC[e4 * 4 + 2] += kc * v4.z; aC[e4 * 4 + 3] += kc * v4.w;
            aS[e4 * 4 + 0] += ks * v4.x; aS[e4 * 4 + 1] += ks * v4.y;
            aS[e4 * 4 + 2] += ks * v4.z; aS[e4 * 4 + 3] += ks * v4.w;
        }
    }

    size_t base = (size_t)(h * NCH + c) * 2 * DDIM * DDIM;
    #pragma unroll
    for (int e = 0; e < 16; e++) {
        g_ckv[base + d * DDIM + eg + e]               = aC[e];
        g_ckv[base + DDIM * DDIM + d * DDIM + eg + e] = aS[e];
    }

    if (tid < DDIM) {
        float sc = 0.f, ss = 0.f;
        for (int i = 0; i < CHUNK; i++) {
            float kd = rk[i * DDIM + tid];
            sc += kd * cw[i];
            ss += kd * sw[i];
        }
        size_t kb = (size_t)(h * NCH + c) * 2 * DDIM;
        g_ck[kb + tid]        = sc;
        g_ck[kb + DDIM + tid] = ss;
    }
}

// ---------------------------------------------------------------------------
// scan: exclusive prefix over 16 chunks (register-prefetched)
// ---------------------------------------------------------------------------
__global__ __launch_bounds__(256)
void scan_kernel() {
    const int h = blockIdx.x, tid = threadIdx.x;
    const int KVSZ = 2 * DDIM * DDIM;
    for (int idx = tid; idx < KVSZ; idx += 256) {
        float v[NCH];
        #pragma unroll
        for (int c = 0; c < NCH; c++)
            v[c] = g_ckv[(size_t)(h * NCH + c) * KVSZ + idx];
        float run = 0.f;
        #pragma unroll
        for (int c = 0; c < NCH; c++) {
            g_pkv[(size_t)(h * NCH + c) * KVSZ + idx] = run;
            run += v[c];
        }
    }
    const int KSZ = 2 * DDIM;
    if (tid < KSZ) {
        float v[NCH];
        #pragma unroll
        for (int c = 0; c < NCH; c++)
            v[c] = g_ck[(size_t)(h * NCH + c) * KSZ + tid];
        float run = 0.f;
        #pragma unroll
        for (int c = 0; c < NCH; c++) {
            g_pk[(size_t)(h * NCH + c) * KSZ + tid] = run;
            run += v[c];
        }
    }
}

// ---------------------------------------------------------------------------
// chunk_out: register-tiled, predicated-causal, fused bf16-split output.
// ---------------------------------------------------------------------------
#define RQT_STRIDE 132
#define S_STRIDE   130

__global__ __launch_bounds__(256, 1)
void chunk_out_kernel() {
    extern __shared__ float smf[];
    float* rqT = smf;                       // [64][132]
    float* rkT = rqT + DDIM * RQT_STRIDE;   // [64][132]
    float* vv  = rkT + DDIM * RQT_STRIDE;   // [128][64]
    float* S   = vv + CHUNK * DDIM;         // [128][130]
    float* KVc = S + CHUNK * S_STRIDE;      // [64][64]
    float* KVs = KVc + DDIM * DDIM;         // [64][64]
    float* K0c = KVs + DDIM * DDIM;         // [64]
    float* K0s = K0c + DDIM;                // [64]
    float* cw  = K0s + DDIM;                // [128]
    float* sw  = cw + CHUNK;                // [128]
    float* nA  = sw + CHUNK;                // [128]
    float* nB  = nA + CHUNK;                // [128]

    const int c = blockIdx.x, h = blockIdx.y, tid = threadIdx.x;

    for (int t = tid; t < CHUNK * DDIM; t += 256) {
        int i = t >> 6, d = t & 63;
        const float* row = g_qkv + (size_t)(c * CHUNK + i) * E3 + h * DDIM;
        rqT[d * RQT_STRIDE + i] = fmaxf(row[d], 0.f);
        rkT[d * RQT_STRIDE + i] = fmaxf(row[EDIM + d], 0.f);
        vv[i * DDIM + d]        = row[2 * EDIM + d];
    }
    if (tid < CHUNK) {
        float th = (float)(c * CHUNK + tid) * THETA_SCALE;
        cw[tid] = cosf(th);
        sw[tid] = sinf(th);
    }
    {
        const float* base = g_pkv + (size_t)(h * NCH + c) * 2 * DDIM * DDIM;
        for (int t = tid; t < 2 * DDIM * DDIM; t += 256) {
            if (t < DDIM * DDIM) KVc[t] = base[t];
            else                 KVs[t - DDIM * DDIM] = base[t];
        }
        const float* kb = g_pk + (size_t)(h * NCH + c) * 2 * DDIM;
        if (tid < 2 * DDIM) {
            if (tid < DDIM) K0c[tid] = kb[tid];
            else            K0s[tid - DDIM] = kb[tid];
        }
    }
    __syncthreads();

    {
        const int ti = tid >> 4, tj = tid & 15;
        const int i0 = ti * 8, j0 = tj * 8;
        if (j0 <= i0 + 7) {
            float acc[8][8];
            #pragma unroll
            for (int r = 0; r < 8; r++)
                #pragma unroll
                for (int q = 0; q < 8; q++) acc[r][q] = 0.f;

            for (int d = 0; d < DDIM; d++) {
                float a[8], b[8];
                #pragma unroll
                for (int r = 0; r < 8; r++) a[r] = rqT[d * RQT_STRIDE + i0 + r];
                #pragma unroll
                for (int r = 0; r < 8; r++) b[r] = rkT[d * RQT_STRIDE + j0 + r];
                #pragma unroll
                for (int r = 0; r < 8; r++)
                    #pragma unroll
                    for (int q = 0; q < 8; q++)
                        acc[r][q] += a[r] * b[q];
            }
            #pragma unroll
            for (int r = 0; r < 8; r++) {
                int i = i0 + r;
                float ci = cw[i], si = sw[i];
                #pragma unroll
                for (int q = 0; q < 8; q++) {
                    int j = j0 + q;
                    if (j <= i)
                        S[i * S_STRIDE + j] = acc[r][q] * (ci * cw[j] + si * sw[j]);
                }
            }
        }
    }
    __syncthreads();

    if (tid < CHUNK) {
        const int i = tid;
        float dc = 0.f, ds = 0.f;
        for (int d = 0; d < DDIM; d++) {
            float q = rqT[d * RQT_STRIDE + i];
            dc += q * K0c[d];
            ds += q * K0s[d];
        }
        float n = cw[i] * dc + sw[i] * ds;
        int jend = (i < 63) ? i : 63;
        for (int j = 0; j <= jend; j++) n += S[i * S_STRIDE + j];
        nA[i] = n;
    } else {
        const int i = tid - CHUNK;
        float n = 0.f;
        for (int j = 64; j <= i; j++) n += S[i * S_STRIDE + j];
        nB[i] = n;
    }
    __syncthreads();

    const int tx = tid & 7, ty = tid >> 3;
    const int e0 = tx * 8, i0 = ty * 4;

    float tC[4][8], tS[4][8], tI[4][8];
    #pragma unroll
    for (int r = 0; r < 4; r++)
        #pragma unroll
        for (int e = 0; e < 8; e++) { tC[r][e] = 0.f; tS[r][e] = 0.f; tI[r][e] = 0.f; }

    for (int d = 0; d < DDIM; d++) {
        float4 q4 = *reinterpret_cast<const float4*>(&rqT[d * RQT_STRIDE + i0]);
        float qr[4] = {q4.x, q4.y, q4.z, q4.w};
        float4 c0 = *reinterpret_cast<const float4*>(&KVc[d * DDIM + e0]);
        float4 c1 = *reinterpret_cast<const float4*>(&KVc[d * DDIM + e0 + 4]);
        float4 s0 = *reinterpret_cast<const float4*>(&KVs[d * DDIM + e0]);
        float4 s1 = *reinterpret_cast<const float4*>(&KVs[d * DDIM + e0 + 4]);
        float cv[8] = {c0.x, c0.y, c0.z, c0.w, c1.x, c1.y, c1.z, c1.w};
        float sv[8] = {s0.x, s0.y, s0.z, s0.w, s1.x, s1.y, s1.z, s1.w};
        #pragma unroll
        for (int r = 0; r < 4; r++)
            #pragma unroll
            for (int e = 0; e < 8; e++) {
                tC[r][e] += qr[r] * cv[e];
                tS[r][e] += qr[r] * sv[e];
            }
    }

    for (int j = 0; j <= i0; j++) {
        float sr[4];
        #pragma unroll
        for (int r = 0; r < 4; r++) sr[r] = S[(i0 + r) * S_STRIDE + j];
        float4 v0 = *reinterpret_cast<const float4*>(&vv[j * DDIM + e0]);
        float4 v1 = *reinterpret_cast<const float4*>(&vv[j * DDIM + e0 + 4]);
        float ve[8] = {v0.x, v0.y, v0.z, v0.w, v1.x, v1.y, v1.z, v1.w};
        #pragma unroll
        for (int r = 0; r < 4; r++)
            #pragma unroll
            for (int e = 0; e < 8; e++)
                tI[r][e] += sr[r] * ve[e];
    }
    #pragma unroll
    for (int dt = 1; dt <= 3; dt++) {
        const int j = i0 + dt;
        float sr[4];
        #pragma unroll
        for (int r = 0; r < 4; r++) {
            float raw = S[(i0 + r) * S_STRIDE + j];
            sr[r] = (dt <= r) ? raw : 0.f;
        }
        float4 v0 = *reinterpret_cast<const float4*>(&vv[j * DDIM + e0]);
        float4 v1 = *reinterpret_cast<const float4*>(&vv[j * DDIM + e0 + 4]);
        float ve[8] = {v0.x, v0.y, v0.z, v0.w, v1.x, v1.y, v1.z, v1.w};
        #pragma unroll
        for (int r = 0; r < 4; r++)
            #pragma unroll
            for (int e = 0; e < 8; e++)
                tI[r][e] += sr[r] * ve[e];
    }

    #pragma unroll
    for (int r = 0; r < 4; r++) {
        const int i = i0 + r;
        float ci = cw[i], si = sw[i];
        float inv = 1.0f / (nA[i] + nB[i] + 1e-6f);
        uint32_t ph[4], pl[4];
        #pragma unroll
        for (int e2 = 0; e2 < 4; e2++) {
            float v0 = (ci * tC[r][e2 * 2 + 0] + si * tS[r][e2 * 2 + 0] + tI[r][e2 * 2 + 0]) * inv;
            float v1 = (ci * tC[r][e2 * 2 + 1] + si * tS[r][e2 * 2 + 1] + tI[r][e2 * 2 + 1]) * inv;
            __nv_bfloat16 h0 = __float2bfloat16(v0);
            __nv_bfloat16 h1 = __float2bfloat16(v1);
            __nv_bfloat16 l0 = __float2bfloat16(v0 - __bfloat162float(h0));
            __nv_bfloat16 l1 = __float2bfloat16(v1 - __bfloat162float(h1));
            ph[e2] = (uint32_t)__bfloat16_as_ushort(h0) |
                     ((uint32_t)__bfloat16_as_ushort(h1) << 16);
            pl[e2] = (uint32_t)__bfloat16_as_ushort(l0) |
                     ((uint32_t)__bfloat16_as_ushort(l1) << 16);
        }
        size_t base = (size_t)(c * CHUNK + i) * EDIM + h * DDIM + e0;
        *reinterpret_cast<uint4*>(&g_ah[base]) = make_uint4(ph[0], ph[1], ph[2], ph[3]);
        *reinterpret_cast<uint4*>(&g_al[base]) = make_uint4(pl[0], pl[1], pl[2], pl[3]);
    }
}

// ---------------------------------------------------------------------------

static const int SMEM_SUM = (2 * CHUNK * DDIM + 2 * CHUNK) * (int)sizeof(float);
static const int SMEM_OUT = (2 * DDIM * RQT_STRIDE + CHUNK * DDIM + CHUNK * S_STRIDE +
                             2 * DDIM * DDIM + 2 * DDIM + 4 * CHUNK) * (int)sizeof(float);

extern "C" void kernel_launch(void* const* d_in, const int* in_sizes, int n_in,
                              void* d_out, int out_size) {
    (void)in_sizes; (void)n_in; (void)out_size;
    const float* x    = (const float*)d_in[0];
    const float* Wqkv = (const float*)d_in[1];
    const float* bqkv = (const float*)d_in[2];
    const float* Wout = (const float*)d_in[3];
    const float* bout = (const float*)d_in[4];
    float* out = (float*)d_out;

    float* qkv_ptr;
    cudaGetSymbolAddress((void**)&qkv_ptr, g_qkv);
    __nv_bfloat16 *xh, *xl, *wqh, *wql, *woh, *wol, *ah, *al;
    cudaGetSymbolAddress((void**)&xh, g_xh);
    cudaGetSymbolAddress((void**)&xl, g_xl);
    cudaGetSymbolAddress((void**)&wqh, g_wqh);
    cudaGetSymbolAddress((void**)&wql, g_wql);
    cudaGetSymbolAddress((void**)&woh, g_woh);
    cudaGetSymbolAddress((void**)&wol, g_wol);
    cudaGetSymbolAddress((void**)&ah, g_ah);
    cudaGetSymbolAddress((void**)&al, g_al);

    cudaFuncSetAttribute(chunk_sum_kernel,
                         cudaFuncAttributeMaxDynamicSharedMemorySize, SMEM_SUM);
    cudaFuncSetAttribute(chunk_out_kernel,
                         cudaFuncAttributeMaxDynamicSharedMemorySize, SMEM_OUT);
    cudaFuncSetAttribute(mma_gemm_kernel<128>,
                         cudaFuncAttributeMaxDynamicSharedMemorySize, GSMEM_128);
    cudaFuncSetAttribute(mma_gemm_kernel<64>,
                         cudaFuncAttributeMaxDynamicSharedMemorySize, GSMEM_64);

    // bf16 splits (inputs)
    split_bf16_kernel<<<(LSEQ * EDIM + 255) / 256, 256>>>(x, xh, xl, LSEQ * EDIM);
    split_bf16_T_kernel<<<dim3(E3 / 32, EDIM / 32), 256>>>(Wqkv, wqh, wql, EDIM, E3);
    split_bf16_T_kernel<<<dim3(EDIM / 32, EDIM / 32), 256>>>(Wout, woh, wol, EDIM, EDIM);

    // 1) QKV GEMM: 128x128 tiles, grid 192, 2 CTAs/SM -> one wave
    mma_gemm_kernel<128><<<dim3(E3 / 128, LSEQ / 128), 256, GSMEM_128>>>(
        xh, xl, wqh, wql, bqkv, qkv_ptr, E3, EDIM);

    // 2) Chunked cosformer attention
    chunk_sum_kernel<<<dim3(NCH, HEADS), 256, SMEM_SUM>>>();
    scan_kernel<<<HEADS, 256>>>();
    chunk_out_kernel<<<dim3(NCH, HEADS), 256, SMEM_OUT>>>();

    // 3) Output GEMM: 64x128 tiles -> grid 128, one wave
    mma_gemm_kernel<64><<<dim3(EDIM / 128, LSEQ / 64), 256, GSMEM_64>>>(
        ah, al, woh, wol, bout, out, EDIM, EDIM);
}

// round 6
// speedup vs baseline: 2.8267x; 1.0709x over previous
#include <cuda_runtime.h>
#include <cuda_bf16.h>
#include <cstdint>
#include <cstddef>

// Problem constants
#define LSEQ 2048
#define EDIM 512
#define HEADS 8
#define DDIM 64
#define E3   1536
#define CHUNK 128
#define NCH  16

#define THETA_SCALE 7.66990393942820573e-4f  // (pi/2)/2048

// ---------------- scratch (device globals; no allocs allowed) ----------------
__device__ float g_qkv[LSEQ * E3];
__device__ float g_ckv[HEADS * NCH * 2 * DDIM * DDIM];
__device__ float g_ck [HEADS * NCH * 2 * DDIM];
__device__ float g_pkv[HEADS * NCH * 2 * DDIM * DDIM];
__device__ float g_pk [HEADS * NCH * 2 * DDIM];

// bf16 split buffers
__device__ __nv_bfloat16 g_xh[LSEQ * EDIM];
__device__ __nv_bfloat16 g_xl[LSEQ * EDIM];
__device__ __nv_bfloat16 g_wqh[E3 * EDIM];   // Wqkv^T  [1536][512]
__device__ __nv_bfloat16 g_wql[E3 * EDIM];
__device__ __nv_bfloat16 g_woh[EDIM * EDIM]; // Wout^T  [512][512]
__device__ __nv_bfloat16 g_wol[EDIM * EDIM];
__device__ __nv_bfloat16 g_ah[LSEQ * EDIM];  // attention out hi/lo
__device__ __nv_bfloat16 g_al[LSEQ * EDIM];

// ---------------- low-level helpers ----------------
__device__ __forceinline__ uint32_t smem_u32(const void* p) {
    uint32_t a;
    asm("{ .reg .u64 t; cvta.to.shared.u64 t, %1; cvt.u32.u64 %0, t; }"
        : "=r"(a) : "l"(p));
    return a;
}
#define CP_ASYNC16(dst, src) \
    asm volatile("cp.async.cg.shared.global [%0], [%1], 16;" :: "r"(dst), "l"(src))
#define CP_COMMIT() asm volatile("cp.async.commit_group;" ::: "memory")
#define CP_WAIT0()  asm volatile("cp.async.wait_group 0;" ::: "memory")
#define CP_WAIT1()  asm volatile("cp.async.wait_group 1;" ::: "memory")

__device__ __forceinline__ void ldmx4(uint32_t* r, uint32_t addr) {
    asm volatile("ldmatrix.sync.aligned.m8n8.x4.shared.b16 {%0,%1,%2,%3}, [%4];"
                 : "=r"(r[0]), "=r"(r[1]), "=r"(r[2]), "=r"(r[3]) : "r"(addr));
}
__device__ __forceinline__ void mma16816(float* c, const uint32_t* a, const uint32_t* b) {
    asm volatile(
        "mma.sync.aligned.m16n8k16.row.col.f32.bf16.bf16.f32 "
        "{%0,%1,%2,%3}, {%4,%5,%6,%7}, {%8,%9}, {%0,%1,%2,%3};"
        : "+f"(c[0]), "+f"(c[1]), "+f"(c[2]), "+f"(c[3])
        : "r"(a[0]), "r"(a[1]), "r"(a[2]), "r"(a[3]), "r"(b[0]), "r"(b[1]));
}

// ---------------- bf16 split conversion kernels ----------------
__global__ __launch_bounds__(256)
void split_bf16_kernel(const float* __restrict__ src,
                       __nv_bfloat16* __restrict__ hi, __nv_bfloat16* __restrict__ lo, int n) {
    int i = blockIdx.x * 256 + threadIdx.x;
    if (i < n) {
        float a = src[i];
        __nv_bfloat16 h = __float2bfloat16(a);
        hi[i] = h;
        lo[i] = __float2bfloat16(a - __bfloat162float(h));
    }
}

// W[K,N] -> WT hi/lo [N,K]  (tiled transpose)
__global__ __launch_bounds__(256)
void split_bf16_T_kernel(const float* __restrict__ W,
                         __nv_bfloat16* __restrict__ hiT, __nv_bfloat16* __restrict__ loT,
                         int K, int N) {
    __shared__ float t[32][33];
    const int tx = threadIdx.x & 31, ty = threadIdx.x >> 5;  // (32, 8)
    const int n0 = blockIdx.x * 32, k0 = blockIdx.y * 32;
    #pragma unroll
    for (int j = 0; j < 4; j++)
        t[ty + 8 * j][tx] = W[(size_t)(k0 + ty + 8 * j) * N + n0 + tx];
    __syncthreads();
    #pragma unroll
    for (int j = 0; j < 4; j++) {
        float a = t[tx][ty + 8 * j];  // = W[k0+tx][n0+ty+8j]
        __nv_bfloat16 h = __float2bfloat16(a);
        size_t o = (size_t)(n0 + ty + 8 * j) * K + k0 + tx;
        hiT[o] = h;
        loT[o] = __float2bfloat16(a - __bfloat162float(h));
    }
}

// ---------------- mma.sync bf16x3 GEMM: C[M,N] = A @ Bt^T + bias --------------
// Templated on BM (CTA tile rows). BN = 128 fixed. 8 warps as 2x4:
// warp tile (BM/2) x 32. K-chunk 32, double-buffered cp.async.
// 3 CTAs/SM so the whole grid is co-resident (no wave quantization).
#define KC 32
#define AST 40   // smem row stride in bf16 elems

template<int BM>
__global__ __launch_bounds__(256, 3)
void mma_gemm_kernel(const __nv_bfloat16* __restrict__ Ah, const __nv_bfloat16* __restrict__ Al,
                     const __nv_bfloat16* __restrict__ Bh, const __nv_bfloat16* __restrict__ Bl,
                     const float* __restrict__ bias, float* __restrict__ C,
                     int N, int K) {
    constexpr int MI = BM / 32;                 // m16-fragments per warp
    constexpr int TILE_A = BM * AST;            // elems
    constexpr int TILE_B = 128 * AST;
    constexpr int BUF_E  = 2 * TILE_A + 2 * TILE_B;

    extern __shared__ __nv_bfloat16 smem[];
    const int tid = threadIdx.x;
    const int wid = tid >> 5, lane = tid & 31;
    const int bn0 = blockIdx.x * 128, bm0 = blockIdx.y * BM;
    const int wm = (wid & 1) * (BM / 2);
    const int wn = (wid >> 1) * 32;

    const uint32_t smb = smem_u32(smem);
    const int NCHK = K / KC;

    float acc[MI][4][4];
    #pragma unroll
    for (int mi = 0; mi < MI; mi++)
        #pragma unroll
        for (int nj = 0; nj < 4; nj++)
            #pragma unroll
            for (int r = 0; r < 4; r++) acc[mi][nj][r] = 0.f;

    // tile layout in each buffer: Ah | Al | Bh | Bl
    const __nv_bfloat16* srcs[4] = {Ah, Al, Bh, Bl};
    const int  srow[4] = {bm0, bm0, bn0, bn0};
    const int  titem[4] = {BM * KC / 8, BM * KC / 8, 128 * KC / 8, 128 * KC / 8};
    const uint32_t toff[4] = {0u, (uint32_t)TILE_A, (uint32_t)(2 * TILE_A),
                              (uint32_t)(2 * TILE_A + TILE_B)};

    auto load_chunk = [&](int b, int k0) {
        #pragma unroll
        for (int t = 0; t < 4; t++) {
            const __nv_bfloat16* s = srcs[t];
            uint32_t dbase = smb + (uint32_t)(b * BUF_E + toff[t]) * 2u;
            const int nit = titem[t];
            for (int item = tid; item < nit; item += 256) {
                int row = item >> 2, sub = item & 3;
                uint32_t d = dbase + (uint32_t)(row * AST + sub * 8) * 2u;
                const void* g = (const void*)(s + (size_t)(srow[t] + row) * K + k0 + sub * 8);
                CP_ASYNC16(d, g);
            }
        }
        CP_COMMIT();
    };

    load_chunk(0, 0);

    for (int c = 0; c < NCHK; c++) {
        const int b = c & 1;
        if (c + 1 < NCHK) {
            load_chunk(b ^ 1, (c + 1) * KC);
            CP_WAIT1();
        } else {
            CP_WAIT0();
        }
        __syncthreads();

        const uint32_t aBh = smb + (uint32_t)(b * BUF_E) * 2u;
        const uint32_t aBl = aBh + (uint32_t)TILE_A * 2u;
        const uint32_t bBh = aBh + (uint32_t)(2 * TILE_A) * 2u;
        const uint32_t bBl = bBh + (uint32_t)TILE_B * 2u;

        #pragma unroll
        for (int ks = 0; ks < KC; ks += 16) {
            const int arow = wm + (lane & 15);
            const int acol = ks + ((lane >> 4) << 3);
            uint32_t ah[MI][4], al[MI][4];
            #pragma unroll
            for (int mi = 0; mi < MI; mi++) {
                uint32_t off = (uint32_t)((arow + mi * 16) * AST + acol) * 2u;
                ldmx4(ah[mi], aBh + off);
                ldmx4(al[mi], aBl + off);
            }
            const int brow = wn + (lane & 7) + ((lane & 16) ? 8 : 0);
            const int bcol = ks + ((lane & 8) ? 8 : 0);
            uint32_t bh[2][4], bl[2][4];
            #pragma unroll
            for (int ni = 0; ni < 2; ni++) {
                uint32_t off = (uint32_t)((brow + ni * 16) * AST + bcol) * 2u;
                ldmx4(bh[ni], bBh + off);
                ldmx4(bl[ni], bBl + off);
            }
            #pragma unroll
            for (int mi = 0; mi < MI; mi++) {
                #pragma unroll
                for (int nj = 0; nj < 4; nj++) {
                    const uint32_t* ph = &bh[nj >> 1][(nj & 1) * 2];
                    const uint32_t* pl = &bl[nj >> 1][(nj & 1) * 2];
                    mma16816(acc[mi][nj], ah[mi], ph);
                    mma16816(acc[mi][nj], ah[mi], pl);
                    mma16816(acc[mi][nj], al[mi], ph);
                }
            }
        }
        __syncthreads();
    }

    const int r0 = bm0 + wm + (lane >> 2);
    const int c0 = bn0 + wn + (lane & 3) * 2;
    #pragma unroll
    for (int mi = 0; mi < MI; mi++) {
        #pragma unroll
        for (int nj = 0; nj < 4; nj++) {
            int row = r0 + mi * 16;
            int col = c0 + nj * 8;
            float b0 = bias[col], b1 = bias[col + 1];
            float2 v0 = make_float2(acc[mi][nj][0] + b0, acc[mi][nj][1] + b1);
            float2 v1 = make_float2(acc[mi][nj][2] + b0, acc[mi][nj][3] + b1);
            *reinterpret_cast<float2*>(&C[(size_t)row * N + col]) = v0;
            *reinterpret_cast<float2*>(&C[(size_t)(row + 8) * N + col]) = v1;
        }
    }
}

// smem byte sizes per instantiation
#define GSMEM_64  (2 * (2 * 64 * AST + 2 * 128 * AST) * 2)    // 61440
#define GSMEM_32  (2 * (2 * 32 * AST + 2 * 128 * AST) * 2)    // 51200

// ---------------------------------------------------------------------------
// chunk_sum: per-chunk KV / K sums
// ---------------------------------------------------------------------------
__global__ __launch_bounds__(256)
void chunk_sum_kernel() {
    extern __shared__ float smf[];
    float* rk = smf;
    float* vv = rk + CHUNK * DDIM;
    float* cw = vv + CHUNK * DDIM;
    float* sw = cw + CHUNK;

    const int c = blockIdx.x, h = blockIdx.y, tid = threadIdx.x;

    for (int t = tid; t < CHUNK * DDIM; t += 256) {
        int i = t >> 6, d = t & 63;
        const float* row = g_qkv + (size_t)(c * CHUNK + i) * E3 + h * DDIM;
        rk[t] = fmaxf(row[EDIM + d], 0.f);
        vv[t] = row[2 * EDIM + d];
    }
    if (tid < CHUNK) {
        float th = (float)(c * CHUNK + tid) * THETA_SCALE;
        cw[tid] = cosf(th);
        sw[tid] = sinf(th);
    }
    __syncthreads();

    const int d  = tid & 63;
    const int eg = (tid >> 6) << 4;
    float aC[16], aS[16];
    #pragma unroll
    for (int e = 0; e < 16; e++) { aC[e] = 0.f; aS[e] = 0.f; }

    for (int i = 0; i < CHUNK; i++) {
        float kd = rk[i * DDIM + d];
        float kc = kd * cw[i];
        float ks = kd * sw[i];
        const float4* vp = reinterpret_cast<const float4*>(&vv[i * DDIM + eg]);
        #pragma unroll
        for (int e4 = 0; e4 < 4; e4++) {
            float4 v4 = vp[e4];
            aC[e4 * 4 + 0] += kc * v4.x; aC[e4 * 4 + 1] += kc * v4.y;
            aC[e4 * 4 + 2] += kc * v4.z; aC[e4 * 4 + 3] += kc * v4.w;
            aS[e4 * 4 + 0] += ks * v4.x; aS[e4 * 4 + 1] += ks * v4.y;
            aS[e4 * 4 + 2] += ks * v4.z; aS[e4 * 4 + 3] += ks * v4.w;
        }
    }

    size_t base = (size_t)(h * NCH + c) * 2 * DDIM * DDIM;
    #pragma unroll
    for (int e = 0; e < 16; e++) {
        g_ckv[base + d * DDIM + eg + e]               = aC[e];
        g_ckv[base + DDIM * DDIM + d * DDIM + eg + e] = aS[e];
    }

    if (tid < DDIM) {
        float sc = 0.f, ss = 0.f;
        for (int i = 0; i < CHUNK; i++) {
            float kd = rk[i * DDIM + tid];
            sc += kd * cw[i];
            ss += kd * sw[i];
        }
        size_t kb = (size_t)(h * NCH + c) * 2 * DDIM;
        g_ck[kb + tid]        = sc;
        g_ck[kb + DDIM + tid] = ss;
    }
}

// ---------------------------------------------------------------------------
// scan: exclusive prefix over 16 chunks (register-prefetched)
// ---------------------------------------------------------------------------
__global__ __launch_bounds__(256)
void scan_kernel() {
    const int h = blockIdx.x, tid = threadIdx.x;
    const int KVSZ = 2 * DDIM * DDIM;
    for (int idx = tid; idx < KVSZ; idx += 256) {
        float v[NCH];
        #pragma unroll
        for (int c = 0; c < NCH; c++)
            v[c] = g_ckv[(size_t)(h * NCH + c) * KVSZ + idx];
        float run = 0.f;
        #pragma unroll
        for (int c = 0; c < NCH; c++) {
            g_pkv[(size_t)(h * NCH + c) * KVSZ + idx] = run;
            run += v[c];
        }
    }
    const int KSZ = 2 * DDIM;
    if (tid < KSZ) {
        float v[NCH];
        #pragma unroll
        for (int c = 0; c < NCH; c++)
            v[c] = g_ck[(size_t)(h * NCH + c) * KSZ + tid];
        float run = 0.f;
        #pragma unroll
        for (int c = 0; c < NCH; c++) {
            g_pk[(size_t)(h * NCH + c) * KSZ + tid] = run;
            run += v[c];
        }
    }
}

// ---------------------------------------------------------------------------
// chunk_out: register-tiled, predicated-causal, fused bf16-split output.
// ---------------------------------------------------------------------------
#define RQT_STRIDE 132
#define S_STRIDE   130

__global__ __launch_bounds__(256, 1)
void chunk_out_kernel() {
    extern __shared__ float smf[];
    float* rqT = smf;                       // [64][132]
    float* rkT = rqT + DDIM * RQT_STRIDE;   // [64][132]
    float* vv  = rkT + DDIM * RQT_STRIDE;   // [128][64]
    float* S   = vv + CHUNK * DDIM;         // [128][130]
    float* KVc = S + CHUNK * S_STRIDE;      // [64][64]
    float* KVs = KVc + DDIM * DDIM;         // [64][64]
    float* K0c = KVs + DDIM * DDIM;         // [64]
    float* K0s = K0c + DDIM;                // [64]
    float* cw  = K0s + DDIM;                // [128]
    float* sw  = cw + CHUNK;                // [128]
    float* nA  = sw + CHUNK;                // [128]
    float* nB  = nA + CHUNK;                // [128]

    const int c = blockIdx.x, h = blockIdx.y, tid = threadIdx.x;

    for (int t = tid; t < CHUNK * DDIM; t += 256) {
        int i = t >> 6, d = t & 63;
        const float* row = g_qkv + (size_t)(c * CHUNK + i) * E3 + h * DDIM;
        rqT[d * RQT_STRIDE + i] = fmaxf(row[d], 0.f);
        rkT[d * RQT_STRIDE + i] = fmaxf(row[EDIM + d], 0.f);
        vv[i * DDIM + d]        = row[2 * EDIM + d];
    }
    if (tid < CHUNK) {
        float th = (float)(c * CHUNK + tid) * THETA_SCALE;
        cw[tid] = cosf(th);
        sw[tid] = sinf(th);
    }
    {
        const float* base = g_pkv + (size_t)(h * NCH + c) * 2 * DDIM * DDIM;
        for (int t = tid; t < 2 * DDIM * DDIM; t += 256) {
            if (t < DDIM * DDIM) KVc[t] = base[t];
            else                 KVs[t - DDIM * DDIM] = base[t];
        }
        const float* kb = g_pk + (size_t)(h * NCH + c) * 2 * DDIM;
        if (tid < 2 * DDIM) {
            if (tid < DDIM) K0c[tid] = kb[tid];
            else            K0s[tid - DDIM] = kb[tid];
        }
    }
    __syncthreads();

    {
        const int ti = tid >> 4, tj = tid & 15;
        const int i0 = ti * 8, j0 = tj * 8;
        if (j0 <= i0 + 7) {
            float acc[8][8];
            #pragma unroll
            for (int r = 0; r < 8; r++)
                #pragma unroll
                for (int q = 0; q < 8; q++) acc[r][q] = 0.f;

            for (int d = 0; d < DDIM; d++) {
                float a[8], b[8];
                #pragma unroll
                for (int r = 0; r < 8; r++) a[r] = rqT[d * RQT_STRIDE + i0 + r];
                #pragma unroll
                for (int r = 0; r < 8; r++) b[r] = rkT[d * RQT_STRIDE + j0 + r];
                #pragma unroll
                for (int r = 0; r < 8; r++)
                    #pragma unroll
                    for (int q = 0; q < 8; q++)
                        acc[r][q] += a[r] * b[q];
            }
            #pragma unroll
            for (int r = 0; r < 8; r++) {
                int i = i0 + r;
                float ci = cw[i], si = sw[i];
                #pragma unroll
                for (int q = 0; q < 8; q++) {
                    int j = j0 + q;
                    if (j <= i)
                        S[i * S_STRIDE + j] = acc[r][q] * (ci * cw[j] + si * sw[j]);
                }
            }
        }
    }
    __syncthreads();

    if (tid < CHUNK) {
        const int i = tid;
        float dc = 0.f, ds = 0.f;
        for (int d = 0; d < DDIM; d++) {
            float q = rqT[d * RQT_STRIDE + i];
            dc += q * K0c[d];
            ds += q * K0s[d];
        }
        float n = cw[i] * dc + sw[i] * ds;
        int jend = (i < 63) ? i : 63;
        for (int j = 0; j <= jend; j++) n += S[i * S_STRIDE + j];
        nA[i] = n;
    } else {
        const int i = tid - CHUNK;
        float n = 0.f;
        for (int j = 64; j <= i; j++) n += S[i * S_STRIDE + j];
        nB[i] = n;
    }
    __syncthreads();

    const int tx = tid & 7, ty = tid >> 3;
    const int e0 = tx * 8, i0 = ty * 4;

    float tC[4][8], tS[4][8], tI[4][8];
    #pragma unroll
    for (int r = 0; r < 4; r++)
        #pragma unroll
        for (int e = 0; e < 8; e++) { tC[r][e] = 0.f; tS[r][e] = 0.f; tI[r][e] = 0.f; }

    for (int d = 0; d < DDIM; d++) {
        float4 q4 = *reinterpret_cast<const float4*>(&rqT[d * RQT_STRIDE + i0]);
        float qr[4] = {q4.x, q4.y, q4.z, q4.w};
        float4 c0 = *reinterpret_cast<const float4*>(&KVc[d * DDIM + e0]);
        float4 c1 = *reinterpret_cast<const float4*>(&KVc[d * DDIM + e0 + 4]);
        float4 s0 = *reinterpret_cast<const float4*>(&KVs[d * DDIM + e0]);
        float4 s1 = *reinterpret_cast<const float4*>(&KVs[d * DDIM + e0 + 4]);
        float cv[8] = {c0.x, c0.y, c0.z, c0.w, c1.x, c1.y, c1.z, c1.w};
        float sv[8] = {s0.x, s0.y, s0.z, s0.w, s1.x, s1.y, s1.z, s1.w};
        #pragma unroll
        for (int r = 0; r < 4; r++)
            #pragma unroll
            for (int e = 0; e < 8; e++) {
                tC[r][e] += qr[r] * cv[e];
                tS[r][e] += qr[r] * sv[e];
            }
    }

    for (int j = 0; j <= i0; j++) {
        float sr[4];
        #pragma unroll
        for (int r = 0; r < 4; r++) sr[r] = S[(i0 + r) * S_STRIDE + j];
        float4 v0 = *reinterpret_cast<const float4*>(&vv[j * DDIM + e0]);
        float4 v1 = *reinterpret_cast<const float4*>(&vv[j * DDIM + e0 + 4]);
        float ve[8] = {v0.x, v0.y, v0.z, v0.w, v1.x, v1.y, v1.z, v1.w};
        #pragma unroll
        for (int r = 0; r < 4; r++)
            #pragma unroll
            for (int e = 0; e < 8; e++)
                tI[r][e] += sr[r] * ve[e];
    }
    #pragma unroll
    for (int dt = 1; dt <= 3; dt++) {
        const int j = i0 + dt;
        float sr[4];
        #pragma unroll
        for (int r = 0; r < 4; r++) {
            float raw = S[(i0 + r) * S_STRIDE + j];
            sr[r] = (dt <= r) ? raw : 0.f;
        }
        float4 v0 = *reinterpret_cast<const float4*>(&vv[j * DDIM + e0]);
        float4 v1 = *reinterpret_cast<const float4*>(&vv[j * DDIM + e0 + 4]);
        float ve[8] = {v0.x, v0.y, v0.z, v0.w, v1.x, v1.y, v1.z, v1.w};
        #pragma unroll
        for (int r = 0; r < 4; r++)
            #pragma unroll
            for (int e = 0; e < 8; e++)
                tI[r][e] += sr[r] * ve[e];
    }

    #pragma unroll
    for (int r = 0; r < 4; r++) {
        const int i = i0 + r;
        float ci = cw[i], si = sw[i];
        float inv = 1.0f / (nA[i] + nB[i] + 1e-6f);
        uint32_t ph[4], pl[4];
        #pragma unroll
        for (int e2 = 0; e2 < 4; e2++) {
            float v0 = (ci * tC[r][e2 * 2 + 0] + si * tS[r][e2 * 2 + 0] + tI[r][e2 * 2 + 0]) * inv;
            float v1 = (ci * tC[r][e2 * 2 + 1] + si * tS[r][e2 * 2 + 1] + tI[r][e2 * 2 + 1]) * inv;
            __nv_bfloat16 h0 = __float2bfloat16(v0);
            __nv_bfloat16 h1 = __float2bfloat16(v1);
            __nv_bfloat16 l0 = __float2bfloat16(v0 - __bfloat162float(h0));
            __nv_bfloat16 l1 = __float2bfloat16(v1 - __bfloat162float(h1));
            ph[e2] = (uint32_t)__bfloat16_as_ushort(h0) |
                     ((uint32_t)__bfloat16_as_ushort(h1) << 16);
            pl[e2] = (uint32_t)__bfloat16_as_ushort(l0) |
                     ((uint32_t)__bfloat16_as_ushort(l1) << 16);
        }
        size_t base = (size_t)(c * CHUNK + i) * EDIM + h * DDIM + e0;
        *reinterpret_cast<uint4*>(&g_ah[base]) = make_uint4(ph[0], ph[1], ph[2], ph[3]);
        *reinterpret_cast<uint4*>(&g_al[base]) = make_uint4(pl[0], pl[1], pl[2], pl[3]);
    }
}

// ---------------------------------------------------------------------------

static const int SMEM_SUM = (2 * CHUNK * DDIM + 2 * CHUNK) * (int)sizeof(float);
static const int SMEM_OUT = (2 * DDIM * RQT_STRIDE + CHUNK * DDIM + CHUNK * S_STRIDE +
                             2 * DDIM * DDIM + 2 * DDIM + 4 * CHUNK) * (int)sizeof(float);

extern "C" void kernel_launch(void* const* d_in, const int* in_sizes, int n_in,
                              void* d_out, int out_size) {
    (void)in_sizes; (void)n_in; (void)out_size;
    const float* x    = (const float*)d_in[0];
    const float* Wqkv = (const float*)d_in[1];
    const float* bqkv = (const float*)d_in[2];
    const float* Wout = (const float*)d_in[3];
    const float* bout = (const float*)d_in[4];
    float* out = (float*)d_out;

    float* qkv_ptr;
    cudaGetSymbolAddress((void**)&qkv_ptr, g_qkv);
    __nv_bfloat16 *xh, *xl, *wqh, *wql, *woh, *wol, *ah, *al;
    cudaGetSymbolAddress((void**)&xh, g_xh);
    cudaGetSymbolAddress((void**)&xl, g_xl);
    cudaGetSymbolAddress((void**)&wqh, g_wqh);
    cudaGetSymbolAddress((void**)&wql, g_wql);
    cudaGetSymbolAddress((void**)&woh, g_woh);
    cudaGetSymbolAddress((void**)&wol, g_wol);
    cudaGetSymbolAddress((void**)&ah, g_ah);
    cudaGetSymbolAddress((void**)&al, g_al);

    cudaFuncSetAttribute(chunk_sum_kernel,
                         cudaFuncAttributeMaxDynamicSharedMemorySize, SMEM_SUM);
    cudaFuncSetAttribute(chunk_out_kernel,
                         cudaFuncAttributeMaxDynamicSharedMemorySize, SMEM_OUT);
    cudaFuncSetAttribute(mma_gemm_kernel<64>,
                         cudaFuncAttributeMaxDynamicSharedMemorySize, GSMEM_64);
    cudaFuncSetAttribute(mma_gemm_kernel<32>,
                         cudaFuncAttributeMaxDynamicSharedMemorySize, GSMEM_32);

    // bf16 splits (inputs)
    split_bf16_kernel<<<(LSEQ * EDIM + 255) / 256, 256>>>(x, xh, xl, LSEQ * EDIM);
    split_bf16_T_kernel<<<dim3(E3 / 32, EDIM / 32), 256>>>(Wqkv, wqh, wql, EDIM, E3);
    split_bf16_T_kernel<<<dim3(EDIM / 32, EDIM / 32), 256>>>(Wout, woh, wol, EDIM, EDIM);

    // 1) QKV GEMM: 64x128 tiles -> grid 384, 3 CTAs/SM -> fully co-resident
    mma_gemm_kernel<64><<<dim3(E3 / 128, LSEQ / 64), 256, GSMEM_64>>>(
        xh, xl, wqh, wql, bqkv, qkv_ptr, E3, EDIM);

    // 2) Chunked cosformer attention
    chunk_sum_kernel<<<dim3(NCH, HEADS), 256, SMEM_SUM>>>();
    scan_kernel<<<HEADS, 256>>>();
    chunk_out_kernel<<<dim3(NCH, HEADS), 256, SMEM_OUT>>>();

    // 3) Output GEMM: 32x128 tiles -> grid 256, fully co-resident
    mma_gemm_kernel<32><<<dim3(EDIM / 128, LSEQ / 32), 256, GSMEM_32>>>(
        ah, al, woh, wol, bout, out, EDIM, EDIM);
}

// round 7
// speedup vs baseline: 3.0570x; 1.0815x over previous
#include <cuda_runtime.h>
#include <cuda_bf16.h>
#include <cstdint>
#include <cstddef>

// Problem constants
#define LSEQ 2048
#define EDIM 512
#define HEADS 8
#define DDIM 64
#define E3   1536
#define CHUNK 64
#define NCH  32

#define THETA_SCALE 7.66990393942820573e-4f  // (pi/2)/2048

// ---------------- scratch (device globals; no allocs allowed) ----------------
__device__ float g_qkv[LSEQ * E3];
__device__ float g_ckv[HEADS * NCH * 2 * DDIM * DDIM];
__device__ float g_ck [HEADS * NCH * 2 * DDIM];
__device__ float g_pkv[HEADS * NCH * 2 * DDIM * DDIM];
__device__ float g_pk [HEADS * NCH * 2 * DDIM];

// bf16 split buffers
__device__ __nv_bfloat16 g_xh[LSEQ * EDIM];
__device__ __nv_bfloat16 g_xl[LSEQ * EDIM];
__device__ __nv_bfloat16 g_wqh[E3 * EDIM];   // Wqkv^T  [1536][512]
__device__ __nv_bfloat16 g_wql[E3 * EDIM];
__device__ __nv_bfloat16 g_woh[EDIM * EDIM]; // Wout^T  [512][512]
__device__ __nv_bfloat16 g_wol[EDIM * EDIM];
__device__ __nv_bfloat16 g_ah[LSEQ * EDIM];  // attention out hi/lo
__device__ __nv_bfloat16 g_al[LSEQ * EDIM];

// ---------------- low-level helpers ----------------
__device__ __forceinline__ uint32_t smem_u32(const void* p) {
    uint32_t a;
    asm("{ .reg .u64 t; cvta.to.shared.u64 t, %1; cvt.u32.u64 %0, t; }"
        : "=r"(a) : "l"(p));
    return a;
}
#define CP_ASYNC16(dst, src) \
    asm volatile("cp.async.cg.shared.global [%0], [%1], 16;" :: "r"(dst), "l"(src))
#define CP_COMMIT() asm volatile("cp.async.commit_group;" ::: "memory")
#define CP_WAIT0()  asm volatile("cp.async.wait_group 0;" ::: "memory")
#define CP_WAIT1()  asm volatile("cp.async.wait_group 1;" ::: "memory")

__device__ __forceinline__ void ldmx4(uint32_t* r, uint32_t addr) {
    asm volatile("ldmatrix.sync.aligned.m8n8.x4.shared.b16 {%0,%1,%2,%3}, [%4];"
                 : "=r"(r[0]), "=r"(r[1]), "=r"(r[2]), "=r"(r[3]) : "r"(addr));
}
__device__ __forceinline__ void mma16816(float* c, const uint32_t* a, const uint32_t* b) {
    asm volatile(
        "mma.sync.aligned.m16n8k16.row.col.f32.bf16.bf16.f32 "
        "{%0,%1,%2,%3}, {%4,%5,%6,%7}, {%8,%9}, {%0,%1,%2,%3};"
        : "+f"(c[0]), "+f"(c[1]), "+f"(c[2]), "+f"(c[3])
        : "r"(a[0]), "r"(a[1]), "r"(a[2]), "r"(a[3]), "r"(b[0]), "r"(b[1]));
}

// ---------------- bf16 split conversion kernels ----------------
__global__ __launch_bounds__(256)
void split_bf16_kernel(const float* __restrict__ src,
                       __nv_bfloat16* __restrict__ hi, __nv_bfloat16* __restrict__ lo, int n) {
    int i = blockIdx.x * 256 + threadIdx.x;
    if (i < n) {
        float a = src[i];
        __nv_bfloat16 h = __float2bfloat16(a);
        hi[i] = h;
        lo[i] = __float2bfloat16(a - __bfloat162float(h));
    }
}

// W[K,N] -> WT hi/lo [N,K]  (tiled transpose)
__global__ __launch_bounds__(256)
void split_bf16_T_kernel(const float* __restrict__ W,
                         __nv_bfloat16* __restrict__ hiT, __nv_bfloat16* __restrict__ loT,
                         int K, int N) {
    __shared__ float t[32][33];
    const int tx = threadIdx.x & 31, ty = threadIdx.x >> 5;  // (32, 8)
    const int n0 = blockIdx.x * 32, k0 = blockIdx.y * 32;
    #pragma unroll
    for (int j = 0; j < 4; j++)
        t[ty + 8 * j][tx] = W[(size_t)(k0 + ty + 8 * j) * N + n0 + tx];
    __syncthreads();
    #pragma unroll
    for (int j = 0; j < 4; j++) {
        float a = t[tx][ty + 8 * j];  // = W[k0+tx][n0+ty+8j]
        __nv_bfloat16 h = __float2bfloat16(a);
        size_t o = (size_t)(n0 + ty + 8 * j) * K + k0 + tx;
        hiT[o] = h;
        loT[o] = __float2bfloat16(a - __bfloat162float(h));
    }
}

// ---------------- mma.sync bf16x3 GEMM (unchanged from R6) --------------
#define KC 32
#define AST 40   // smem row stride in bf16 elems

template<int BM>
__global__ __launch_bounds__(256, 3)
void mma_gemm_kernel(const __nv_bfloat16* __restrict__ Ah, const __nv_bfloat16* __restrict__ Al,
                     const __nv_bfloat16* __restrict__ Bh, const __nv_bfloat16* __restrict__ Bl,
                     const float* __restrict__ bias, float* __restrict__ C,
                     int N, int K) {
    constexpr int MI = BM / 32;
    constexpr int TILE_A = BM * AST;
    constexpr int TILE_B = 128 * AST;
    constexpr int BUF_E  = 2 * TILE_A + 2 * TILE_B;

    extern __shared__ __nv_bfloat16 smem[];
    const int tid = threadIdx.x;
    const int wid = tid >> 5, lane = tid & 31;
    const int bn0 = blockIdx.x * 128, bm0 = blockIdx.y * BM;
    const int wm = (wid & 1) * (BM / 2);
    const int wn = (wid >> 1) * 32;

    const uint32_t smb = smem_u32(smem);
    const int NCHK = K / KC;

    float acc[MI][4][4];
    #pragma unroll
    for (int mi = 0; mi < MI; mi++)
        #pragma unroll
        for (int nj = 0; nj < 4; nj++)
            #pragma unroll
            for (int r = 0; r < 4; r++) acc[mi][nj][r] = 0.f;

    const __nv_bfloat16* srcs[4] = {Ah, Al, Bh, Bl};
    const int  srow[4] = {bm0, bm0, bn0, bn0};
    const int  titem[4] = {BM * KC / 8, BM * KC / 8, 128 * KC / 8, 128 * KC / 8};
    const uint32_t toff[4] = {0u, (uint32_t)TILE_A, (uint32_t)(2 * TILE_A),
                              (uint32_t)(2 * TILE_A + TILE_B)};

    auto load_chunk = [&](int b, int k0) {
        #pragma unroll
        for (int t = 0; t < 4; t++) {
            const __nv_bfloat16* s = srcs[t];
            uint32_t dbase = smb + (uint32_t)(b * BUF_E + toff[t]) * 2u;
            const int nit = titem[t];
            for (int item = tid; item < nit; item += 256) {
                int row = item >> 2, sub = item & 3;
                uint32_t d = dbase + (uint32_t)(row * AST + sub * 8) * 2u;
                const void* g = (const void*)(s + (size_t)(srow[t] + row) * K + k0 + sub * 8);
                CP_ASYNC16(d, g);
            }
        }
        CP_COMMIT();
    };

    load_chunk(0, 0);

    for (int c = 0; c < NCHK; c++) {
        const int b = c & 1;
        if (c + 1 < NCHK) {
            load_chunk(b ^ 1, (c + 1) * KC);
            CP_WAIT1();
        } else {
            CP_WAIT0();
        }
        __syncthreads();

        const uint32_t aBh = smb + (uint32_t)(b * BUF_E) * 2u;
        const uint32_t aBl = aBh + (uint32_t)TILE_A * 2u;
        const uint32_t bBh = aBh + (uint32_t)(2 * TILE_A) * 2u;
        const uint32_t bBl = bBh + (uint32_t)TILE_B * 2u;

        #pragma unroll
        for (int ks = 0; ks < KC; ks += 16) {
            const int arow = wm + (lane & 15);
            const int acol = ks + ((lane >> 4) << 3);
            uint32_t ah[MI][4], al[MI][4];
            #pragma unroll
            for (int mi = 0; mi < MI; mi++) {
                uint32_t off = (uint32_t)((arow + mi * 16) * AST + acol) * 2u;
                ldmx4(ah[mi], aBh + off);
                ldmx4(al[mi], aBl + off);
            }
            const int brow = wn + (lane & 7) + ((lane & 16) ? 8 : 0);
            const int bcol = ks + ((lane & 8) ? 8 : 0);
            uint32_t bh[2][4], bl[2][4];
            #pragma unroll
            for (int ni = 0; ni < 2; ni++) {
                uint32_t off = (uint32_t)((brow + ni * 16) * AST + bcol) * 2u;
                ldmx4(bh[ni], bBh + off);
                ldmx4(bl[ni], bBl + off);
            }
            #pragma unroll
            for (int mi = 0; mi < MI; mi++) {
                #pragma unroll
                for (int nj = 0; nj < 4; nj++) {
                    const uint32_t* ph = &bh[nj >> 1][(nj & 1) * 2];
                    const uint32_t* pl = &bl[nj >> 1][(nj & 1) * 2];
                    mma16816(acc[mi][nj], ah[mi], ph);
                    mma16816(acc[mi][nj], ah[mi], pl);
                    mma16816(acc[mi][nj], al[mi], ph);
                }
            }
        }
        __syncthreads();
    }

    const int r0 = bm0 + wm + (lane >> 2);
    const int c0 = bn0 + wn + (lane & 3) * 2;
    #pragma unroll
    for (int mi = 0; mi < MI; mi++) {
        #pragma unroll
        for (int nj = 0; nj < 4; nj++) {
            int row = r0 + mi * 16;
            int col = c0 + nj * 8;
            float b0 = bias[col], b1 = bias[col + 1];
            float2 v0 = make_float2(acc[mi][nj][0] + b0, acc[mi][nj][1] + b1);
            float2 v1 = make_float2(acc[mi][nj][2] + b0, acc[mi][nj][3] + b1);
            *reinterpret_cast<float2*>(&C[(size_t)row * N + col]) = v0;
            *reinterpret_cast<float2*>(&C[(size_t)(row + 8) * N + col]) = v1;
        }
    }
}

#define GSMEM_64  (2 * (2 * 64 * AST + 2 * 128 * AST) * 2)    // 61440
#define GSMEM_32  (2 * (2 * 32 * AST + 2 * 128 * AST) * 2)    // 51200

// ---------------------------------------------------------------------------
// chunk_sum: per-chunk (C=64) KV / K sums. grid (NCH, HEADS) = 256 blocks.
// ---------------------------------------------------------------------------
__global__ __launch_bounds__(256)
void chunk_sum_kernel() {
    extern __shared__ float smf[];
    float* rk = smf;                 // [64][64]
    float* vv = rk + CHUNK * DDIM;   // [64][64]
    float* cw = vv + CHUNK * DDIM;   // [64]
    float* sw = cw + CHUNK;          // [64]

    const int c = blockIdx.x, h = blockIdx.y, tid = threadIdx.x;

    for (int t = tid; t < CHUNK * DDIM; t += 256) {
        int i = t >> 6, d = t & 63;
        const float* row = g_qkv + (size_t)(c * CHUNK + i) * E3 + h * DDIM;
        rk[t] = fmaxf(row[EDIM + d], 0.f);
        vv[t] = row[2 * EDIM + d];
    }
    if (tid < CHUNK) {
        float th = (float)(c * CHUNK + tid) * THETA_SCALE;
        cw[tid] = cosf(th);
        sw[tid] = sinf(th);
    }
    __syncthreads();

    const int d  = tid & 63;
    const int eg = (tid >> 6) << 4;
    float aC[16], aS[16];
    #pragma unroll
    for (int e = 0; e < 16; e++) { aC[e] = 0.f; aS[e] = 0.f; }

    for (int i = 0; i < CHUNK; i++) {
        float kd = rk[i * DDIM + d];
        float kc = kd * cw[i];
        float ks = kd * sw[i];
        const float4* vp = reinterpret_cast<const float4*>(&vv[i * DDIM + eg]);
        #pragma unroll
        for (int e4 = 0; e4 < 4; e4++) {
            float4 v4 = vp[e4];
            aC[e4 * 4 + 0] += kc * v4.x; aC[e4 * 4 + 1] += kc * v4.y;
            aC[e4 * 4 + 2] += kc * v4.z; aC[e4 * 4 + 3] += kc * v4.w;
            aS[e4 * 4 + 0] += ks * v4.x; aS[e4 * 4 + 1] += ks * v4.y;
            aS[e4 * 4 + 2] += ks * v4.z; aS[e4 * 4 + 3] += ks * v4.w;
        }
    }

    size_t base = (size_t)(h * NCH + c) * 2 * DDIM * DDIM;
    #pragma unroll
    for (int e = 0; e < 16; e++) {
        g_ckv[base + d * DDIM + eg + e]               = aC[e];
        g_ckv[base + DDIM * DDIM + d * DDIM + eg + e] = aS[e];
    }

    if (tid < DDIM) {
        float sc = 0.f, ss = 0.f;
        for (int i = 0; i < CHUNK; i++) {
            float kd = rk[i * DDIM + tid];
            sc += kd * cw[i];
            ss += kd * sw[i];
        }
        size_t kb = (size_t)(h * NCH + c) * 2 * DDIM;
        g_ck[kb + tid]        = sc;
        g_ck[kb + DDIM + tid] = ss;
    }
}

// ---------------------------------------------------------------------------
// scan: exclusive prefix over 32 chunks. grid 256 blocks x 256 threads,
// one thread per scan lane (h = blk>>5, idx = (blk&31)*256 + tid).
// ---------------------------------------------------------------------------
__global__ __launch_bounds__(256)
void scan_kernel() {
    const int h = blockIdx.x >> 5;
    const int idx = (blockIdx.x & 31) * 256 + threadIdx.x;  // 0..8191
    const int KVSZ = 2 * DDIM * DDIM;  // 8192

    float v[NCH];
    #pragma unroll
    for (int c = 0; c < NCH; c++)
        v[c] = g_ckv[(size_t)(h * NCH + c) * KVSZ + idx];
    float run = 0.f;
    #pragma unroll
    for (int c = 0; c < NCH; c++) {
        g_pkv[(size_t)(h * NCH + c) * KVSZ + idx] = run;
        run += v[c];
    }

    if ((blockIdx.x & 31) == 0 && threadIdx.x < 2 * DDIM) {
        const int t = threadIdx.x;
        const int KSZ = 2 * DDIM;
        float w[NCH];
        #pragma unroll
        for (int c = 0; c < NCH; c++)
            w[c] = g_ck[(size_t)(h * NCH + c) * KSZ + t];
        float r2 = 0.f;
        #pragma unroll
        for (int c = 0; c < NCH; c++) {
            g_pk[(size_t)(h * NCH + c) * KSZ + t] = r2;
            r2 += w[c];
        }
    }
}

// ---------------------------------------------------------------------------
// chunk_out (C=64): register-tiled, predicated-causal, fused bf16-split out.
// grid (NCH, HEADS) = 256 blocks, 256 threads.
// ---------------------------------------------------------------------------
#define RQT_STRIDE 68
#define S_STRIDE   66

__global__ __launch_bounds__(256)
void chunk_out_kernel() {
    extern __shared__ float smf[];
    float* rqT = smf;                       // [64][68]
    float* rkT = rqT + DDIM * RQT_STRIDE;   // [64][68]
    float* vv  = rkT + DDIM * RQT_STRIDE;   // [64][64]
    float* S   = vv + CHUNK * DDIM;         // [64][66]
    float* KVc = S + CHUNK * S_STRIDE;      // [64][64]
    float* KVs = KVc + DDIM * DDIM;         // [64][64]
    float* K0c = KVs + DDIM * DDIM;         // [64]
    float* K0s = K0c + DDIM;                // [64]
    float* cw  = K0s + DDIM;                // [64]
    float* sw  = cw + CHUNK;                // [64]
    float* nrm = sw + CHUNK;                // [64]

    const int c = blockIdx.x, h = blockIdx.y, tid = threadIdx.x;

    for (int t = tid; t < CHUNK * DDIM; t += 256) {
        int i = t >> 6, d = t & 63;
        const float* row = g_qkv + (size_t)(c * CHUNK + i) * E3 + h * DDIM;
        rqT[d * RQT_STRIDE + i] = fmaxf(row[d], 0.f);
        rkT[d * RQT_STRIDE + i] = fmaxf(row[EDIM + d], 0.f);
        vv[i * DDIM + d]        = row[2 * EDIM + d];
    }
    if (tid < CHUNK) {
        float th = (float)(c * CHUNK + tid) * THETA_SCALE;
        cw[tid] = cosf(th);
        sw[tid] = sinf(th);
    }
    {
        const float* base = g_pkv + (size_t)(h * NCH + c) * 2 * DDIM * DDIM;
        for (int t = tid; t < 2 * DDIM * DDIM; t += 256) {
            if (t < DDIM * DDIM) KVc[t] = base[t];
            else                 KVs[t - DDIM * DDIM] = base[t];
        }
        const float* kb = g_pk + (size_t)(h * NCH + c) * 2 * DDIM;
        if (tid < 2 * DDIM) {
            if (tid < DDIM) K0c[tid] = kb[tid];
            else            K0s[tid - DDIM] = kb[tid];
        }
    }
    __syncthreads();

    // ---- phase 1: S[i][j] (j<=i), 4x4 tiles on a 16x16 thread grid
    {
        const int ti = tid >> 4, tj = tid & 15;
        const int i0 = ti * 4, j0 = tj * 4;
        if (j0 <= i0 + 3) {
            float acc[4][4];
            #pragma unroll
            for (int r = 0; r < 4; r++)
                #pragma unroll
                for (int q = 0; q < 4; q++) acc[r][q] = 0.f;

            for (int d = 0; d < DDIM; d++) {
                float4 a4 = *reinterpret_cast<const float4*>(&rqT[d * RQT_STRIDE + i0]);
                float4 b4 = *reinterpret_cast<const float4*>(&rkT[d * RQT_STRIDE + j0]);
                float a[4] = {a4.x, a4.y, a4.z, a4.w};
                float b[4] = {b4.x, b4.y, b4.z, b4.w};
                #pragma unroll
                for (int r = 0; r < 4; r++)
                    #pragma unroll
                    for (int q = 0; q < 4; q++)
                        acc[r][q] += a[r] * b[q];
            }
            #pragma unroll
            for (int r = 0; r < 4; r++) {
                int i = i0 + r;
                float ci = cw[i], si = sw[i];
                #pragma unroll
                for (int q = 0; q < 4; q++) {
                    int j = j0 + q;
                    if (j <= i)
                        S[i * S_STRIDE + j] = acc[r][q] * (ci * cw[j] + si * sw[j]);
                }
            }
        }
    }
    __syncthreads();

    // ---- phase 2: nrm (rows 0..63 across first 64 threads)
    if (tid < CHUNK) {
        const int i = tid;
        float dc = 0.f, ds = 0.f;
        for (int d = 0; d < DDIM; d++) {
            float q = rqT[d * RQT_STRIDE + i];
            dc += q * K0c[d];
            ds += q * K0s[d];
        }
        float n = cw[i] * dc + sw[i] * ds;
        for (int j = 0; j <= i; j++) n += S[i * S_STRIDE + j];
        nrm[i] = n;
    }
    __syncthreads();

    // ---- phase 3: 2 rows x 8 cols per thread
    const int tx = tid & 7, ty = tid >> 3;   // ty 0..31
    const int e0 = tx * 8, i0 = ty * 2;

    float tC[2][8], tS[2][8], tI[2][8];
    #pragma unroll
    for (int r = 0; r < 2; r++)
        #pragma unroll
        for (int e = 0; e < 8; e++) { tC[r][e] = 0.f; tS[r][e] = 0.f; tI[r][e] = 0.f; }

    for (int d = 0; d < DDIM; d++) {
        float2 q2 = *reinterpret_cast<const float2*>(&rqT[d * RQT_STRIDE + i0]);
        float qr[2] = {q2.x, q2.y};
        float4 c0 = *reinterpret_cast<const float4*>(&KVc[d * DDIM + e0]);
        float4 c1 = *reinterpret_cast<const float4*>(&KVc[d * DDIM + e0 + 4]);
        float4 s0 = *reinterpret_cast<const float4*>(&KVs[d * DDIM + e0]);
        float4 s1 = *reinterpret_cast<const float4*>(&KVs[d * DDIM + e0 + 4]);
        float cv[8] = {c0.x, c0.y, c0.z, c0.w, c1.x, c1.y, c1.z, c1.w};
        float sv[8] = {s0.x, s0.y, s0.z, s0.w, s1.x, s1.y, s1.z, s1.w};
        #pragma unroll
        for (int r = 0; r < 2; r++)
            #pragma unroll
            for (int e = 0; e < 8; e++) {
                tC[r][e] += qr[r] * cv[e];
                tS[r][e] += qr[r] * sv[e];
            }
    }

    for (int j = 0; j <= i0; j++) {
        float sr[2];
        #pragma unroll
        for (int r = 0; r < 2; r++) sr[r] = S[(i0 + r) * S_STRIDE + j];
        float4 v0 = *reinterpret_cast<const float4*>(&vv[j * DDIM + e0]);
        float4 v1 = *reinterpret_cast<const float4*>(&vv[j * DDIM + e0 + 4]);
        float ve[8] = {v0.x, v0.y, v0.z, v0.w, v1.x, v1.y, v1.z, v1.w};
        #pragma unroll
        for (int r = 0; r < 2; r++)
            #pragma unroll
            for (int e = 0; e < 8; e++)
                tI[r][e] += sr[r] * ve[e];
    }
    {   // tail j = i0+1, valid only for r=1
        const int j = i0 + 1;
        float s1 = S[(i0 + 1) * S_STRIDE + j];
        float4 v0 = *reinterpret_cast<const float4*>(&vv[j * DDIM + e0]);
        float4 v1 = *reinterpret_cast<const float4*>(&vv[j * DDIM + e0 + 4]);
        float ve[8] = {v0.x, v0.y, v0.z, v0.w, v1.x, v1.y, v1.z, v1.w};
        #pragma unroll
        for (int e = 0; e < 8; e++)
            tI[1][e] += s1 * ve[e];
    }

    // ---- epilogue: combine, normalize, bf16 hi/lo split, store
    #pragma unroll
    for (int r = 0; r < 2; r++) {
        const int i = i0 + r;
        float ci = cw[i], si = sw[i];
        float inv = 1.0f / (nrm[i] + 1e-6f);
        uint32_t ph[4], pl[4];
        #pragma unroll
        for (int e2 = 0; e2 < 4; e2++) {
            float v0 = (ci * tC[r][e2 * 2 + 0] + si * tS[r][e2 * 2 + 0] + tI[r][e2 * 2 + 0]) * inv;
            float v1 = (ci * tC[r][e2 * 2 + 1] + si * tS[r][e2 * 2 + 1] + tI[r][e2 * 2 + 1]) * inv;
            __nv_bfloat16 h0 = __float2bfloat16(v0);
            __nv_bfloat16 h1 = __float2bfloat16(v1);
            __nv_bfloat16 l0 = __float2bfloat16(v0 - __bfloat162float(h0));
            __nv_bfloat16 l1 = __float2bfloat16(v1 - __bfloat162float(h1));
            ph[e2] = (uint32_t)__bfloat16_as_ushort(h0) |
                     ((uint32_t)__bfloat16_as_ushort(h1) << 16);
            pl[e2] = (uint32_t)__bfloat16_as_ushort(l0) |
                     ((uint32_t)__bfloat16_as_ushort(l1) << 16);
        }
        size_t base = (size_t)(c * CHUNK + i) * EDIM + h * DDIM + e0;
        *reinterpret_cast<uint4*>(&g_ah[base]) = make_uint4(ph[0], ph[1], ph[2], ph[3]);
        *reinterpret_cast<uint4*>(&g_al[base]) = make_uint4(pl[0], pl[1], pl[2], pl[3]);
    }
}

// ---------------------------------------------------------------------------

static const int SMEM_SUM = (2 * CHUNK * DDIM + 2 * CHUNK) * (int)sizeof(float);
static const int SMEM_OUT = (2 * DDIM * RQT_STRIDE + CHUNK * DDIM + CHUNK * S_STRIDE +
                             2 * DDIM * DDIM + 2 * DDIM + 3 * CHUNK) * (int)sizeof(float);

extern "C" void kernel_launch(void* const* d_in, const int* in_sizes, int n_in,
                              void* d_out, int out_size) {
    (void)in_sizes; (void)n_in; (void)out_size;
    const float* x    = (const float*)d_in[0];
    const float* Wqkv = (const float*)d_in[1];
    const float* bqkv = (const float*)d_in[2];
    const float* Wout = (const float*)d_in[3];
    const float* bout = (const float*)d_in[4];
    float* out = (float*)d_out;

    float* qkv_ptr;
    cudaGetSymbolAddress((void**)&qkv_ptr, g_qkv);
    __nv_bfloat16 *xh, *xl, *wqh, *wql, *woh, *wol, *ah, *al;
    cudaGetSymbolAddress((void**)&xh, g_xh);
    cudaGetSymbolAddress((void**)&xl, g_xl);
    cudaGetSymbolAddress((void**)&wqh, g_wqh);
    cudaGetSymbolAddress((void**)&wql, g_wql);
    cudaGetSymbolAddress((void**)&woh, g_woh);
    cudaGetSymbolAddress((void**)&wol, g_wol);
    cudaGetSymbolAddress((void**)&ah, g_ah);
    cudaGetSymbolAddress((void**)&al, g_al);

    cudaFuncSetAttribute(chunk_sum_kernel,
                         cudaFuncAttributeMaxDynamicSharedMemorySize, SMEM_SUM);
    cudaFuncSetAttribute(chunk_out_kernel,
                         cudaFuncAttributeMaxDynamicSharedMemorySize, SMEM_OUT);
    cudaFuncSetAttribute(mma_gemm_kernel<64>,
                         cudaFuncAttributeMaxDynamicSharedMemorySize, GSMEM_64);
    cudaFuncSetAttribute(mma_gemm_kernel<32>,
                         cudaFuncAttributeMaxDynamicSharedMemorySize, GSMEM_32);

    // bf16 splits (inputs)
    split_bf16_kernel<<<(LSEQ * EDIM + 255) / 256, 256>>>(x, xh, xl, LSEQ * EDIM);
    split_bf16_T_kernel<<<dim3(E3 / 32, EDIM / 32), 256>>>(Wqkv, wqh, wql, EDIM, E3);
    split_bf16_T_kernel<<<dim3(EDIM / 32, EDIM / 32), 256>>>(Wout, woh, wol, EDIM, EDIM);

    // 1) QKV GEMM: 64x128 tiles -> grid 384, 3 CTAs/SM
    mma_gemm_kernel<64><<<dim3(E3 / 128, LSEQ / 64), 256, GSMEM_64>>>(
        xh, xl, wqh, wql, bqkv, qkv_ptr, E3, EDIM);

    // 2) Chunked cosformer attention (C=64, 256-block grids)
    chunk_sum_kernel<<<dim3(NCH, HEADS), 256, SMEM_SUM>>>();
    scan_kernel<<<256, 256>>>();
    chunk_out_kernel<<<dim3(NCH, HEADS), 256, SMEM_OUT>>>();

    // 3) Output GEMM: 32x128 tiles -> grid 256
    mma_gemm_kernel<32><<<dim3(EDIM / 128, LSEQ / 32), 256, GSMEM_32>>>(
        ah, al, woh, wol, bout, out, EDIM, EDIM);
}